// round 1
// baseline (speedup 1.0000x reference)
#include <cuda_runtime.h>

// SConv: conv3x3(128->256, pad1) + BN + SiLU  ->  y (identity)
//        shift(4 groups, +/-1 px) + conv1x1(256->256, bias) + BN + y + SiLU -> out
// Shapes: B=16, C1=128, C2=256, H=W=128, all fp32.
// Strategy R0: fp32 baseline with packed fma.rn.f32x2 (2 FMA/instr) to double
// fp32 throughput. Two kernels through a __device__ scratch buffer.

#define B_  16
#define C1  128
#define C2  256
#define H_  128
#define W_  128
#define EPSBN 1e-5f

typedef unsigned long long ull;
typedef unsigned int uint;

// 268 MB scratch for the intermediate y (post conv3x3+BN+SiLU).
__device__ float g_y[(size_t)B_ * C2 * H_ * W_];

__device__ __forceinline__ ull pk(float lo, float hi) {
    ull r;
    asm("mov.b64 %0, {%1, %2};" : "=l"(r)
        : "r"(__float_as_uint(lo)), "r"(__float_as_uint(hi)));
    return r;
}
__device__ __forceinline__ float2 upk(ull v) {
    uint lo, hi;
    asm("mov.b64 {%0, %1}, %2;" : "=r"(lo), "=r"(hi) : "l"(v));
    return make_float2(__uint_as_float(lo), __uint_as_float(hi));
}
// Packed dual-FMA: acc.{lo,hi} += a.{lo,hi} * b.{lo,hi}
#define FMA2(acc, a, b) \
    asm("fma.rn.f32x2 %0, %1, %2, %0;" : "+l"(acc) : "l"(a), "l"(b))

__device__ __forceinline__ float silu_f(float v) {
    return v / (1.0f + __expf(-v));
}

// ---------------------------------------------------------------------------
// Kernel 1: conv3x3 + BN + SiLU -> g_y
// Block tile: 16 oc x 8 h x 128 w. 256 threads: r = tid>>5 (row), cg = tid&31
// (4-col group). Each thread: 16 oc x 4 cols = 32 accumulators (16 f32x2 pairs x2).
// ---------------------------------------------------------------------------
__global__ __launch_bounds__(256) void k_conv3(
    const float* __restrict__ x, const float* __restrict__ wc,
    const float* __restrict__ gamma, const float* __restrict__ beta,
    const float* __restrict__ mean, const float* __restrict__ var)
{
    __shared__ __align__(16) float sx[2][10][132];   // 2 ic, 10 rows, 130 cols (+pad)
    __shared__ ull swu[2][16][9];                    // weights duplicated (w,w)

    const int tid = threadIdx.x;
    const int r   = tid >> 5;     // 0..7  output row within tile
    const int cg  = tid & 31;     // 0..31 column group (4 cols)
    const int h0  = blockIdx.x * 8;
    const int oc0 = blockIdx.y * 16;
    const int b   = blockIdx.z;

    ull acc[16][2];
#pragma unroll
    for (int o = 0; o < 16; ++o) { acc[o][0] = 0ULL; acc[o][1] = 0ULL; }

    const float* xb = x + (size_t)b * C1 * H_ * W_;

    for (int c1 = 0; c1 < C1; c1 += 2) {
        // ---- stage x tile: 2 x 10 x 130, zero-padded at borders ----
        for (int idx = tid; idx < 2 * 10 * 130; idx += 256) {
            int ck  = idx / 1300;
            int rem = idx - ck * 1300;
            int lr  = rem / 130;
            int lc  = rem - lr * 130;
            int gh  = h0 - 1 + lr;
            int gw  = lc - 1;
            float v = 0.0f;
            if ((uint)gh < (uint)H_ && (uint)gw < (uint)W_)
                v = __ldg(&xb[((size_t)(c1 + ck) * H_ + gh) * W_ + gw]);
            sx[ck][lr][lc] = v;
        }
        // ---- stage weights (duplicated pairs for FFMA2) ----
        for (int idx = tid; idx < 2 * 16 * 9; idx += 256) {
            int ck  = idx / 144;
            int rem = idx - ck * 144;
            int o   = rem / 9;
            int k   = rem - o * 9;
            float v = __ldg(&wc[((size_t)(oc0 + o) * C1 + (c1 + ck)) * 9 + k]);
            swu[ck][o][k] = pk(v, v);
        }
        __syncthreads();

#pragma unroll
        for (int ck = 0; ck < 2; ++ck) {
            // x window: rows r..r+2, cols 4cg..4cg+5 packed as pairs
            // P[dy] = {(c0,c1),(c2,c3),(c4,c5),(c1,c2),(c3,c4)}
            ull P[3][5];
#pragma unroll
            for (int dy = 0; dy < 3; ++dy) {
                const float* row = &sx[ck][r + dy][cg * 4];
                float4 A  = *(const float4*)row;        // c0..c3
                float2 Bv = *(const float2*)(row + 4);  // c4,c5
                P[dy][0] = pk(A.x, A.y);
                P[dy][1] = pk(A.z, A.w);
                P[dy][2] = pk(Bv.x, Bv.y);
                P[dy][3] = pk(A.y, A.z);
                P[dy][4] = pk(A.w, Bv.x);
            }
#pragma unroll
            for (int o = 0; o < 16; ++o) {
                const ull* wp = swu[ck][o];
#pragma unroll
                for (int dy = 0; dy < 3; ++dy) {
                    ull w0 = wp[dy * 3 + 0];
                    ull w1 = wp[dy * 3 + 1];
                    ull w2 = wp[dy * 3 + 2];
                    FMA2(acc[o][0], P[dy][0], w0);   // dx=0, cols 0-1 / 2-3
                    FMA2(acc[o][1], P[dy][1], w0);
                    FMA2(acc[o][0], P[dy][3], w1);   // dx=1, cols 1-2 / 3-4
                    FMA2(acc[o][1], P[dy][4], w1);
                    FMA2(acc[o][0], P[dy][1], w2);   // dx=2, cols 2-3 / 4-5
                    FMA2(acc[o][1], P[dy][2], w2);
                }
            }
        }
        __syncthreads();
    }

    // ---- epilogue: BN + SiLU, store y ----
    const int h = h0 + r;
#pragma unroll
    for (int o = 0; o < 16; ++o) {
        int oc = oc0 + o;
        float inv = gamma[oc] * rsqrtf(var[oc] + EPSBN);
        float bb  = beta[oc] - mean[oc] * inv;
        float2 v0 = upk(acc[o][0]);
        float2 v1 = upk(acc[o][1]);
        float4 out4;
        out4.x = silu_f(v0.x * inv + bb);
        out4.y = silu_f(v0.y * inv + bb);
        out4.z = silu_f(v1.x * inv + bb);
        out4.w = silu_f(v1.y * inv + bb);
        *(float4*)&g_y[(((size_t)b * C2 + oc) * H_ + h) * W_ + cg * 4] = out4;
    }
}

// ---------------------------------------------------------------------------
// Kernel 2: shift + conv1x1 + bias + BN + identity + SiLU -> out
// GEMM tile: 64 oc x 128 px (one image row), K=256 in chunks of 32.
// Shift folded into the smem gather (per channel group +/-1 px, zero fill).
// Thread: tm = tid>>5 -> 8 ocs [tm*8..tm*8+8), tn = tid&31 -> cols 4tn..4tn+3.
// ---------------------------------------------------------------------------
__global__ __launch_bounds__(256) void k_pw(
    const float* __restrict__ w1, const float* __restrict__ b1,
    const float* __restrict__ gamma, const float* __restrict__ beta,
    const float* __restrict__ mean, const float* __restrict__ var,
    float* __restrict__ out)
{
    __shared__ __align__(16) float syf[32][128];  // shifted y, one K-chunk
    __shared__ ull sw2[32][64];                   // duplicated weights [k][m]

    const int tid = threadIdx.x;
    const int tm  = tid >> 5;
    const int tn  = tid & 31;
    const int oc0 = blockIdx.x * 64;
    const int h   = blockIdx.y;
    const int b   = blockIdx.z;

    ull acc[8][2];
#pragma unroll
    for (int m = 0; m < 8; ++m) { acc[m][0] = 0ULL; acc[m][1] = 0ULL; }

    const float* yb = g_y + (size_t)b * C2 * H_ * W_;

    for (int kc0 = 0; kc0 < C2; kc0 += 32) {
        // ---- gather shifted y tile (shift by channel group) ----
#pragma unroll
        for (int i = 0; i < 16; ++i) {
            int idx = tid + i * 256;        // 4096 elements
            int kk  = idx >> 7;
            int w   = idx & 127;
            int ic  = kc0 + kk;
            int g   = ic >> 6;              // group of 64 channels
            int sh = h, sw_ = w;
            bool valid = true;
            if      (g == 0) { sw_ = w - 1; valid = (sw_ >= 0);  }  // src w-1
            else if (g == 1) { sh  = h + 1; valid = (sh < H_);   }  // src h+1
            else if (g == 2) { sw_ = w + 1; valid = (sw_ < W_);  }  // src w+1
            else             { sh  = h - 1; valid = (sh >= 0);   }  // src h-1
            syf[kk][w] = valid ? __ldg(&yb[((size_t)ic * H_ + sh) * W_ + sw_]) : 0.0f;
        }
        // ---- stage weights duplicated ----
#pragma unroll
        for (int i = 0; i < 8; ++i) {
            int idx = tid + i * 256;        // 2048 elements
            int mm  = idx >> 5;
            int kk  = idx & 31;
            float v = __ldg(&w1[(size_t)(oc0 + mm) * C2 + (kc0 + kk)]);
            sw2[kk][mm] = pk(v, v);
        }
        __syncthreads();

#pragma unroll
        for (int kk = 0; kk < 32; ++kk) {
            const ull* yrow = (const ull*)syf[kk];
            ull y0 = yrow[2 * tn];
            ull y1 = yrow[2 * tn + 1];
            const ull* wr = &sw2[kk][tm * 8];
#pragma unroll
            for (int m = 0; m < 8; ++m) {
                ull wd = wr[m];
                FMA2(acc[m][0], y0, wd);
                FMA2(acc[m][1], y1, wd);
            }
        }
        __syncthreads();
    }

    // ---- epilogue: +bias, BN, +identity, SiLU ----
    const size_t pbase = (((size_t)b * C2 + oc0 + tm * 8) * H_ + h) * W_ + tn * 4;
#pragma unroll
    for (int m = 0; m < 8; ++m) {
        int oc    = oc0 + tm * 8 + m;
        float inv = gamma[oc] * rsqrtf(var[oc] + EPSBN);
        float bb  = beta[oc] - mean[oc] * inv;
        float bs  = b1[oc];
        float2 v0 = upk(acc[m][0]);
        float2 v1 = upk(acc[m][1]);
        size_t off = pbase + (size_t)m * H_ * W_;
        float4 idn = *(const float4*)&g_y[off];
        float4 o4;
        float z;
        z = (v0.x + bs) * inv + bb + idn.x; o4.x = silu_f(z);
        z = (v0.y + bs) * inv + bb + idn.y; o4.y = silu_f(z);
        z = (v1.x + bs) * inv + bb + idn.z; o4.z = silu_f(z);
        z = (v1.y + bs) * inv + bb + idn.w; o4.w = silu_f(z);
        *(float4*)&out[off] = o4;
    }
}

// ---------------------------------------------------------------------------
extern "C" void kernel_launch(void* const* d_in, const int* in_sizes, int n_in,
                              void* d_out, int out_size)
{
    const float* x     = (const float*)d_in[0];
    const float* wconv = (const float*)d_in[1];
    const float* w1    = (const float*)d_in[2];
    const float* b1    = (const float*)d_in[3];
    const float* gamma = (const float*)d_in[4];
    const float* beta  = (const float*)d_in[5];
    const float* mean  = (const float*)d_in[6];
    const float* var   = (const float*)d_in[7];
    float* out = (float*)d_out;

    dim3 g1(H_ / 8, C2 / 16, B_);   // 16 x 16 x 16 blocks
    k_conv3<<<g1, 256>>>(x, wconv, gamma, beta, mean, var);

    dim3 g2(C2 / 64, H_, B_);       // 4 x 128 x 16 blocks
    k_pw<<<g2, 256>>>(w1, b1, gamma, beta, mean, var, out);
}

// round 2
// speedup vs baseline: 1.0000x; 1.0000x over previous
#include <cuda_runtime.h>

// SConv: conv3x3(128->256, pad1) + BN + SiLU  ->  y (identity)
//        shift(4 groups, +/-1 px) + conv1x1(256->256, bias) + BN + y + SiLU -> out
// Shapes: B=16, C1=128, C2=256, H=W=128, all fp32.
// Strategy R0: fp32 baseline with packed fma.rn.f32x2 (2 FMA/instr) to double
// fp32 throughput. Two kernels through a __device__ scratch buffer.

#define B_  16
#define C1  128
#define C2  256
#define H_  128
#define W_  128
#define EPSBN 1e-5f

typedef unsigned long long ull;
typedef unsigned int uint;

// 268 MB scratch for the intermediate y (post conv3x3+BN+SiLU).
__device__ float g_y[(size_t)B_ * C2 * H_ * W_];

__device__ __forceinline__ ull pk(float lo, float hi) {
    ull r;
    asm("mov.b64 %0, {%1, %2};" : "=l"(r)
        : "r"(__float_as_uint(lo)), "r"(__float_as_uint(hi)));
    return r;
}
__device__ __forceinline__ float2 upk(ull v) {
    uint lo, hi;
    asm("mov.b64 {%0, %1}, %2;" : "=r"(lo), "=r"(hi) : "l"(v));
    return make_float2(__uint_as_float(lo), __uint_as_float(hi));
}
// Packed dual-FMA: acc.{lo,hi} += a.{lo,hi} * b.{lo,hi}
#define FMA2(acc, a, b) \
    asm("fma.rn.f32x2 %0, %1, %2, %0;" : "+l"(acc) : "l"(a), "l"(b))

__device__ __forceinline__ float silu_f(float v) {
    return v / (1.0f + __expf(-v));
}

// ---------------------------------------------------------------------------
// Kernel 1: conv3x3 + BN + SiLU -> g_y
// Block tile: 16 oc x 8 h x 128 w. 256 threads: r = tid>>5 (row), cg = tid&31
// (4-col group). Each thread: 16 oc x 4 cols = 32 accumulators (16 f32x2 pairs x2).
// ---------------------------------------------------------------------------
__global__ __launch_bounds__(256) void k_conv3(
    const float* __restrict__ x, const float* __restrict__ wc,
    const float* __restrict__ gamma, const float* __restrict__ beta,
    const float* __restrict__ mean, const float* __restrict__ var)
{
    __shared__ __align__(16) float sx[2][10][132];   // 2 ic, 10 rows, 130 cols (+pad)
    __shared__ ull swu[2][16][9];                    // weights duplicated (w,w)

    const int tid = threadIdx.x;
    const int r   = tid >> 5;     // 0..7  output row within tile
    const int cg  = tid & 31;     // 0..31 column group (4 cols)
    const int h0  = blockIdx.x * 8;
    const int oc0 = blockIdx.y * 16;
    const int b   = blockIdx.z;

    ull acc[16][2];
#pragma unroll
    for (int o = 0; o < 16; ++o) { acc[o][0] = 0ULL; acc[o][1] = 0ULL; }

    const float* xb = x + (size_t)b * C1 * H_ * W_;

    for (int c1 = 0; c1 < C1; c1 += 2) {
        // ---- stage x tile: 2 x 10 x 130, zero-padded at borders ----
        for (int idx = tid; idx < 2 * 10 * 130; idx += 256) {
            int ck  = idx / 1300;
            int rem = idx - ck * 1300;
            int lr  = rem / 130;
            int lc  = rem - lr * 130;
            int gh  = h0 - 1 + lr;
            int gw  = lc - 1;
            float v = 0.0f;
            if ((uint)gh < (uint)H_ && (uint)gw < (uint)W_)
                v = __ldg(&xb[((size_t)(c1 + ck) * H_ + gh) * W_ + gw]);
            sx[ck][lr][lc] = v;
        }
        // ---- stage weights (duplicated pairs for FFMA2) ----
        for (int idx = tid; idx < 2 * 16 * 9; idx += 256) {
            int ck  = idx / 144;
            int rem = idx - ck * 144;
            int o   = rem / 9;
            int k   = rem - o * 9;
            float v = __ldg(&wc[((size_t)(oc0 + o) * C1 + (c1 + ck)) * 9 + k]);
            swu[ck][o][k] = pk(v, v);
        }
        __syncthreads();

#pragma unroll
        for (int ck = 0; ck < 2; ++ck) {
            // x window: rows r..r+2, cols 4cg..4cg+5 packed as pairs
            // P[dy] = {(c0,c1),(c2,c3),(c4,c5),(c1,c2),(c3,c4)}
            ull P[3][5];
#pragma unroll
            for (int dy = 0; dy < 3; ++dy) {
                const float* row = &sx[ck][r + dy][cg * 4];
                float4 A  = *(const float4*)row;        // c0..c3
                float2 Bv = *(const float2*)(row + 4);  // c4,c5
                P[dy][0] = pk(A.x, A.y);
                P[dy][1] = pk(A.z, A.w);
                P[dy][2] = pk(Bv.x, Bv.y);
                P[dy][3] = pk(A.y, A.z);
                P[dy][4] = pk(A.w, Bv.x);
            }
#pragma unroll
            for (int o = 0; o < 16; ++o) {
                const ull* wp = swu[ck][o];
#pragma unroll
                for (int dy = 0; dy < 3; ++dy) {
                    ull w0 = wp[dy * 3 + 0];
                    ull w1 = wp[dy * 3 + 1];
                    ull w2 = wp[dy * 3 + 2];
                    FMA2(acc[o][0], P[dy][0], w0);   // dx=0, cols 0-1 / 2-3
                    FMA2(acc[o][1], P[dy][1], w0);
                    FMA2(acc[o][0], P[dy][3], w1);   // dx=1, cols 1-2 / 3-4
                    FMA2(acc[o][1], P[dy][4], w1);
                    FMA2(acc[o][0], P[dy][1], w2);   // dx=2, cols 2-3 / 4-5
                    FMA2(acc[o][1], P[dy][2], w2);
                }
            }
        }
        __syncthreads();
    }

    // ---- epilogue: BN + SiLU, store y ----
    const int h = h0 + r;
#pragma unroll
    for (int o = 0; o < 16; ++o) {
        int oc = oc0 + o;
        float inv = gamma[oc] * rsqrtf(var[oc] + EPSBN);
        float bb  = beta[oc] - mean[oc] * inv;
        float2 v0 = upk(acc[o][0]);
        float2 v1 = upk(acc[o][1]);
        float4 out4;
        out4.x = silu_f(v0.x * inv + bb);
        out4.y = silu_f(v0.y * inv + bb);
        out4.z = silu_f(v1.x * inv + bb);
        out4.w = silu_f(v1.y * inv + bb);
        *(float4*)&g_y[(((size_t)b * C2 + oc) * H_ + h) * W_ + cg * 4] = out4;
    }
}

// ---------------------------------------------------------------------------
// Kernel 2: shift + conv1x1 + bias + BN + identity + SiLU -> out
// GEMM tile: 64 oc x 128 px (one image row), K=256 in chunks of 32.
// Shift folded into the smem gather (per channel group +/-1 px, zero fill).
// Thread: tm = tid>>5 -> 8 ocs [tm*8..tm*8+8), tn = tid&31 -> cols 4tn..4tn+3.
// ---------------------------------------------------------------------------
__global__ __launch_bounds__(256) void k_pw(
    const float* __restrict__ w1, const float* __restrict__ b1,
    const float* __restrict__ gamma, const float* __restrict__ beta,
    const float* __restrict__ mean, const float* __restrict__ var,
    float* __restrict__ out)
{
    __shared__ __align__(16) float syf[32][128];  // shifted y, one K-chunk
    __shared__ ull sw2[32][64];                   // duplicated weights [k][m]

    const int tid = threadIdx.x;
    const int tm  = tid >> 5;
    const int tn  = tid & 31;
    const int oc0 = blockIdx.x * 64;
    const int h   = blockIdx.y;
    const int b   = blockIdx.z;

    ull acc[8][2];
#pragma unroll
    for (int m = 0; m < 8; ++m) { acc[m][0] = 0ULL; acc[m][1] = 0ULL; }

    const float* yb = g_y + (size_t)b * C2 * H_ * W_;

    for (int kc0 = 0; kc0 < C2; kc0 += 32) {
        // ---- gather shifted y tile (shift by channel group) ----
#pragma unroll
        for (int i = 0; i < 16; ++i) {
            int idx = tid + i * 256;        // 4096 elements
            int kk  = idx >> 7;
            int w   = idx & 127;
            int ic  = kc0 + kk;
            int g   = ic >> 6;              // group of 64 channels
            int sh = h, sw_ = w;
            bool valid = true;
            if      (g == 0) { sw_ = w - 1; valid = (sw_ >= 0);  }  // src w-1
            else if (g == 1) { sh  = h + 1; valid = (sh < H_);   }  // src h+1
            else if (g == 2) { sw_ = w + 1; valid = (sw_ < W_);  }  // src w+1
            else             { sh  = h - 1; valid = (sh >= 0);   }  // src h-1
            syf[kk][w] = valid ? __ldg(&yb[((size_t)ic * H_ + sh) * W_ + sw_]) : 0.0f;
        }
        // ---- stage weights duplicated ----
#pragma unroll
        for (int i = 0; i < 8; ++i) {
            int idx = tid + i * 256;        // 2048 elements
            int mm  = idx >> 5;
            int kk  = idx & 31;
            float v = __ldg(&w1[(size_t)(oc0 + mm) * C2 + (kc0 + kk)]);
            sw2[kk][mm] = pk(v, v);
        }
        __syncthreads();

#pragma unroll
        for (int kk = 0; kk < 32; ++kk) {
            const ull* yrow = (const ull*)syf[kk];
            ull y0 = yrow[2 * tn];
            ull y1 = yrow[2 * tn + 1];
            const ull* wr = &sw2[kk][tm * 8];
#pragma unroll
            for (int m = 0; m < 8; ++m) {
                ull wd = wr[m];
                FMA2(acc[m][0], y0, wd);
                FMA2(acc[m][1], y1, wd);
            }
        }
        __syncthreads();
    }

    // ---- epilogue: +bias, BN, +identity, SiLU ----
    const size_t pbase = (((size_t)b * C2 + oc0 + tm * 8) * H_ + h) * W_ + tn * 4;
#pragma unroll
    for (int m = 0; m < 8; ++m) {
        int oc    = oc0 + tm * 8 + m;
        float inv = gamma[oc] * rsqrtf(var[oc] + EPSBN);
        float bb  = beta[oc] - mean[oc] * inv;
        float bs  = b1[oc];
        float2 v0 = upk(acc[m][0]);
        float2 v1 = upk(acc[m][1]);
        size_t off = pbase + (size_t)m * H_ * W_;
        float4 idn = *(const float4*)&g_y[off];
        float4 o4;
        float z;
        z = (v0.x + bs) * inv + bb + idn.x; o4.x = silu_f(z);
        z = (v0.y + bs) * inv + bb + idn.y; o4.y = silu_f(z);
        z = (v1.x + bs) * inv + bb + idn.z; o4.z = silu_f(z);
        z = (v1.y + bs) * inv + bb + idn.w; o4.w = silu_f(z);
        *(float4*)&out[off] = o4;
    }
}

// ---------------------------------------------------------------------------
extern "C" void kernel_launch(void* const* d_in, const int* in_sizes, int n_in,
                              void* d_out, int out_size)
{
    const float* x     = (const float*)d_in[0];
    const float* wconv = (const float*)d_in[1];
    const float* w1    = (const float*)d_in[2];
    const float* b1    = (const float*)d_in[3];
    const float* gamma = (const float*)d_in[4];
    const float* beta  = (const float*)d_in[5];
    const float* mean  = (const float*)d_in[6];
    const float* var   = (const float*)d_in[7];
    float* out = (float*)d_out;

    dim3 g1(H_ / 8, C2 / 16, B_);   // 16 x 16 x 16 blocks
    k_conv3<<<g1, 256>>>(x, wconv, gamma, beta, mean, var);

    dim3 g2(C2 / 64, H_, B_);       // 4 x 128 x 16 blocks
    k_pw<<<g2, 256>>>(w1, b1, gamma, beta, mean, var, out);
}

// round 4
// speedup vs baseline: 7.3549x; 7.3546x over previous
#include <cuda_runtime.h>

// SConv via mma.sync tf32 (sm_80-portable PTX -> HMMA on sm_103).
// conv3x3+BN+SiLU -> g_y ; shift+conv1x1+bias+BN+identity+SiLU -> out
// B=16, C1=128, C2=256, H=W=128, fp32.
//
// Implicit GEMM: D[128 oc][256 px] += A[128x32] @ B[32x256] per chunk.
//   conv3x3: 36 chunks (9 taps x 4 ic-chunks), tap shift folded into B gather.
//   conv1x1: 8 chunks, channel-group shift folded into B gather.
// CTA = 256 thr (8 warps, 2Mx4N), warp tile 64x64, mma m16n8k8 tf32.
// Weights pre-repacked into per-lane fragment order (LDS.128/LDS.64 frags).

#define B_  16
#define C1  128
#define C2  256
#define H_  128
#define W_  128
#define HW  (H_*W_)
#define EPSBN 1e-5f

typedef unsigned int uint;

__device__ float g_y[(size_t)B_ * C2 * H_ * W_];  // identity (post conv3x3+BN+SiLU)
__device__ float g_wA[36 * 2 * 4096];             // conv w, frag order, tf32-rounded
__device__ float g_wB[8 * 2 * 4096];              // 1x1 w, frag order, tf32-rounded

__device__ __forceinline__ uint tf32b(float x) {
    uint u;
    asm("cvt.rna.tf32.f32 %0, %1;" : "=r"(u) : "f"(x));
    return u;
}
__device__ __forceinline__ float silu_f(float v) { return v / (1.0f + __expf(-v)); }

#define MMA8(d, a, b) \
    asm volatile("mma.sync.aligned.m16n8k8.row.col.f32.tf32.tf32.f32 " \
        "{%0,%1,%2,%3}, {%4,%5,%6,%7}, {%8,%9}, {%0,%1,%2,%3};" \
        : "+f"((d)[0]), "+f"((d)[1]), "+f"((d)[2]), "+f"((d)[3]) \
        : "r"((a).x), "r"((a).y), "r"((a).z), "r"((a).w), "r"((b).x), "r"((b).y))

// ------------------------------------------------- one-time weight repacks --
// frag dst index within a 16KB (4096-float) A-chunk tile [M=128][K=32]:
//   kstep=kk>>3, kin=kk&7, mblock=m>>4, min=m&15
//   lane=(min&7)*4+(kin&3), word=(kin>>2)*2+(min>>3)
//   idx = (kstep*8+mblock)*128 + lane*4 + word
__device__ __forceinline__ int fragidx(int m, int kk) {
    int kstep = kk >> 3, kin = kk & 7, mblock = m >> 4, mn = m & 15;
    int lane = (mn & 7) * 4 + (kin & 3);
    int word = ((kin >> 2) << 1) + (mn >> 3);
    return ((kstep << 3) + mblock) * 128 + lane * 4 + word;
}

__global__ __launch_bounds__(256) void k_repack_conv(const float* __restrict__ wc) {
    int idx = blockIdx.x * 256 + threadIdx.x;           // over 256*128*9
    if (idx >= C2 * C1 * 9) return;
    int tap = idx % 9, rest = idx / 9;
    int ic  = rest % C1, oc = rest / C1;
    float v = wc[idx];
    int kc = ic >> 5, kk = ic & 31;
    int it = kc * 9 + tap;
    int ocg = oc >> 7, m = oc & 127;
    g_wA[(size_t)(it * 2 + ocg) * 4096 + fragidx(m, kk)] = __uint_as_float(tf32b(v));
}

__global__ __launch_bounds__(256) void k_repack_pw(const float* __restrict__ w1) {
    int idx = blockIdx.x * 256 + threadIdx.x;           // over 256*256
    if (idx >= C2 * C2) return;
    int ic = idx % C2, oc = idx / C2;
    float v = w1[idx];
    int kc = ic >> 5, kk = ic & 31;
    int ocg = oc >> 7, m = oc & 127;
    g_wB[(size_t)(kc * 2 + ocg) * 4096 + fragidx(m, kk)] = __uint_as_float(tf32b(v));
}

// ------------------------------------------------------------ GEMM pieces --
// smem: A chunk 16KB ([kstep*8+mblock][lane]{4 words}), B chunk 32KB
//       ([kstep*32+nblock][lane]{2 words}); double buffered = 96KB.
#define A_BYTES 16384
#define B_BYTES 32768
#define DSMEM_BYTES (2 * (A_BYTES + B_BYTES))

struct PfA { uint4 v[4]; };
struct PfB { float v[16][2]; };

__device__ __forceinline__ void ldgA(const float* __restrict__ src, int tid, PfA& p) {
    const uint4* s4 = (const uint4*)src;
#pragma unroll
    for (int i = 0; i < 4; ++i) p.v[i] = __ldg(&s4[tid + i * 256]);
}
__device__ __forceinline__ void stsA(char* dst, int tid, const PfA& p) {
    uint4* d4 = (uint4*)dst;
#pragma unroll
    for (int i = 0; i < 4; ++i) d4[tid + i * 256] = p.v[i];
}
__device__ __forceinline__ void stsB(char* dst, int wrp, int lane, const PfB& p) {
#pragma unroll
    for (int j = 0; j < 16; ++j) {
        int g = wrp + (j << 3);
        uint2 v = make_uint2(tf32b(p.v[j][0]), tf32b(p.v[j][1]));
        *(uint2*)(dst + ((size_t)(g * 32 + lane) << 3)) = v;
    }
}

// B gather for conv3x3 chunk it (kc=it/9, tap=it%9), tile rows h0..h0+1
__device__ __forceinline__ void ldgB_conv(const float* __restrict__ xb, int it,
                                          int h0, int wrp, int lane, PfB& p) {
    const int kc = it / 9, tap = it - kc * 9;
    const int ky = tap / 3, kx = tap - ky * 3;
    const int kbase = kc * 32;
#pragma unroll
    for (int j = 0; j < 16; ++j) {
        int g  = wrp + (j << 3);
        int n  = ((g & 31) << 3) + (lane >> 2);
        int kk = ((g >> 5) << 3) + (lane & 3);
        int hh = h0 + (n >> 7) + ky - 1;
        int ww = (n & 127) + kx - 1;
        bool ok = ((uint)hh < (uint)H_) && ((uint)ww < (uint)W_);
        const float* ptr = xb + (size_t)(kbase + kk) * HW + hh * W_ + ww;
        p.v[j][0] = ok ? __ldg(ptr) : 0.0f;
        p.v[j][1] = ok ? __ldg(ptr + 4 * HW) : 0.0f;
    }
}

// B gather for pw chunk kc with per-64ch-group shift
__device__ __forceinline__ void ldgB_pw(const float* __restrict__ yb, int kc,
                                        int h0, int wrp, int lane, PfB& p) {
    const int grp = kc >> 1;
    const int kbase = kc * 32;
#pragma unroll
    for (int j = 0; j < 16; ++j) {
        int g  = wrp + (j << 3);
        int n  = ((g & 31) << 3) + (lane >> 2);
        int kk = ((g >> 5) << 3) + (lane & 3);
        int hh = h0 + (n >> 7);
        int ww = n & 127;
        bool ok;
        if      (grp == 0) { ww -= 1; ok = ww >= 0;  }
        else if (grp == 1) { hh += 1; ok = hh < H_;  }
        else if (grp == 2) { ww += 1; ok = ww < W_;  }
        else               { hh -= 1; ok = hh >= 0;  }
        const float* ptr = yb + (size_t)(kbase + kk) * HW + hh * W_ + ww;
        p.v[j][0] = ok ? __ldg(ptr) : 0.0f;
        p.v[j][1] = ok ? __ldg(ptr + 4 * HW) : 0.0f;
    }
}

__device__ __forceinline__ void mma_chunk(const char* Ab, const char* Bb,
                                          int wm, int wn, int lane,
                                          float acc[4][8][4]) {
#pragma unroll
    for (int ks = 0; ks < 4; ++ks) {
        uint4 a[4];
#pragma unroll
        for (int mf = 0; mf < 4; ++mf)
            a[mf] = *(const uint4*)(Ab + ((size_t)((ks * 8 + wm * 4 + mf) * 32 + lane) << 4));
        uint2 bf[8];
#pragma unroll
        for (int nf = 0; nf < 8; ++nf)
            bf[nf] = *(const uint2*)(Bb + ((size_t)((ks * 32 + wn * 8 + nf) * 32 + lane) << 3));
#pragma unroll
        for (int mf = 0; mf < 4; ++mf)
#pragma unroll
            for (int nf = 0; nf < 8; ++nf)
                MMA8(acc[mf][nf], a[mf], bf[nf]);
    }
}

// ------------------------------------------------------ conv3x3 + BN + SiLU
__global__ __launch_bounds__(256, 1) void k_conv3(
    const float* __restrict__ x,
    const float* __restrict__ gamma, const float* __restrict__ beta,
    const float* __restrict__ mean,  const float* __restrict__ var)
{
    extern __shared__ __align__(16) char dsm[];
    char* A0 = dsm;               char* A1 = dsm + A_BYTES;
    char* Bb0 = dsm + 2 * A_BYTES; char* Bb1 = Bb0 + B_BYTES;

    const int tid = threadIdx.x;
    const int wrp = tid >> 5, lane = tid & 31;
    const int wm = wrp >> 2, wn = wrp & 3;
    const int h0  = blockIdx.x * 2;
    const int oc0 = blockIdx.y * 128;
    const int ocg = blockIdx.y;
    const int b   = blockIdx.z;

    const float* xb = x + (size_t)b * C1 * HW;

    float acc[4][8][4];
#pragma unroll
    for (int i = 0; i < 4; ++i)
#pragma unroll
        for (int j = 0; j < 8; ++j)
#pragma unroll
            for (int q = 0; q < 4; ++q) acc[i][j][q] = 0.0f;

    PfA pa; PfB pb;
    // prologue: stage chunk 0
    ldgA(g_wA + (size_t)(0 * 2 + ocg) * 4096, tid, pa);
    ldgB_conv(xb, 0, h0, wrp, lane, pb);
    stsA(A0, tid, pa);
    stsB(Bb0, wrp, lane, pb);
    __syncthreads();

#pragma unroll 1
    for (int it = 0; it < 36; ++it) {
        const bool pf = (it + 1) < 36;
        if (pf) {
            ldgA(g_wA + (size_t)((it + 1) * 2 + ocg) * 4096, tid, pa);
            ldgB_conv(xb, it + 1, h0, wrp, lane, pb);
        }
        const int cur = it & 1;
        mma_chunk(cur ? A1 : A0, cur ? Bb1 : Bb0, wm, wn, lane, acc);
        if (pf) {
            stsA(cur ? A0 : A1, tid, pa);
            stsB(cur ? Bb0 : Bb1, wrp, lane, pb);
        }
        __syncthreads();
    }

    // epilogue: BN + SiLU -> g_y
#pragma unroll
    for (int mf = 0; mf < 4; ++mf) {
        const int m0 = wm * 64 + mf * 16 + (lane >> 2);
        const int oc_a = oc0 + m0, oc_b = oc_a + 8;
        const float inva = __ldg(&gamma[oc_a]) * rsqrtf(__ldg(&var[oc_a]) + EPSBN);
        const float bba  = __ldg(&beta[oc_a]) - __ldg(&mean[oc_a]) * inva;
        const float invb = __ldg(&gamma[oc_b]) * rsqrtf(__ldg(&var[oc_b]) + EPSBN);
        const float bbb  = __ldg(&beta[oc_b]) - __ldg(&mean[oc_b]) * invb;
        float* pa_ = g_y + ((size_t)b * C2 + oc_a) * HW;
        float* pb_ = g_y + ((size_t)b * C2 + oc_b) * HW;
#pragma unroll
        for (int nf = 0; nf < 8; ++nf) {
            const int n = wn * 64 + nf * 8 + (lane & 3) * 2;
            const int off = (h0 + (n >> 7)) * W_ + (n & 127);
            float2 u, v;
            u.x = silu_f(acc[mf][nf][0] * inva + bba);
            u.y = silu_f(acc[mf][nf][1] * inva + bba);
            v.x = silu_f(acc[mf][nf][2] * invb + bbb);
            v.y = silu_f(acc[mf][nf][3] * invb + bbb);
            *(float2*)(pa_ + off) = u;
            *(float2*)(pb_ + off) = v;
        }
    }
}

// --------------------------- shift + conv1x1 + bias + BN + identity + SiLU
__global__ __launch_bounds__(256, 1) void k_pw(
    const float* __restrict__ b1,
    const float* __restrict__ gamma, const float* __restrict__ beta,
    const float* __restrict__ mean,  const float* __restrict__ var,
    float* __restrict__ out)
{
    extern __shared__ __align__(16) char dsm[];
    char* A0 = dsm;               char* A1 = dsm + A_BYTES;
    char* Bb0 = dsm + 2 * A_BYTES; char* Bb1 = Bb0 + B_BYTES;

    const int tid = threadIdx.x;
    const int wrp = tid >> 5, lane = tid & 31;
    const int wm = wrp >> 2, wn = wrp & 3;
    const int h0  = blockIdx.x * 2;
    const int oc0 = blockIdx.y * 128;
    const int ocg = blockIdx.y;
    const int b   = blockIdx.z;

    const float* yb = g_y + (size_t)b * C2 * HW;

    float acc[4][8][4];
#pragma unroll
    for (int i = 0; i < 4; ++i)
#pragma unroll
        for (int j = 0; j < 8; ++j)
#pragma unroll
            for (int q = 0; q < 4; ++q) acc[i][j][q] = 0.0f;

    PfA pa; PfB pb;
    ldgA(g_wB + (size_t)(0 * 2 + ocg) * 4096, tid, pa);
    ldgB_pw(yb, 0, h0, wrp, lane, pb);
    stsA(A0, tid, pa);
    stsB(Bb0, wrp, lane, pb);
    __syncthreads();

#pragma unroll 1
    for (int it = 0; it < 8; ++it) {
        const bool pf = (it + 1) < 8;
        if (pf) {
            ldgA(g_wB + (size_t)((it + 1) * 2 + ocg) * 4096, tid, pa);
            ldgB_pw(yb, it + 1, h0, wrp, lane, pb);
        }
        const int cur = it & 1;
        mma_chunk(cur ? A1 : A0, cur ? Bb1 : Bb0, wm, wn, lane, acc);
        if (pf) {
            stsA(cur ? A0 : A1, tid, pa);
            stsB(cur ? Bb0 : Bb1, wrp, lane, pb);
        }
        __syncthreads();
    }

    // epilogue: +bias, BN, +identity, SiLU -> out
#pragma unroll
    for (int mf = 0; mf < 4; ++mf) {
        const int m0 = wm * 64 + mf * 16 + (lane >> 2);
        const int oc_a = oc0 + m0, oc_b = oc_a + 8;
        const float inva = __ldg(&gamma[oc_a]) * rsqrtf(__ldg(&var[oc_a]) + EPSBN);
        const float bba  = __ldg(&beta[oc_a]) - __ldg(&mean[oc_a]) * inva;
        const float bsa  = __ldg(&b1[oc_a]);
        const float invb = __ldg(&gamma[oc_b]) * rsqrtf(__ldg(&var[oc_b]) + EPSBN);
        const float bbb  = __ldg(&beta[oc_b]) - __ldg(&mean[oc_b]) * invb;
        const float bsb  = __ldg(&b1[oc_b]);
        const size_t ra = ((size_t)b * C2 + oc_a) * HW;
        const size_t rb = ((size_t)b * C2 + oc_b) * HW;
#pragma unroll
        for (int nf = 0; nf < 8; ++nf) {
            const int n = wn * 64 + nf * 8 + (lane & 3) * 2;
            const int off = (h0 + (n >> 7)) * W_ + (n & 127);
            float2 ida = *(const float2*)(g_y + ra + off);
            float2 idb = *(const float2*)(g_y + rb + off);
            float2 u, v; float z;
            z = (acc[mf][nf][0] + bsa) * inva + bba + ida.x; u.x = silu_f(z);
            z = (acc[mf][nf][1] + bsa) * inva + bba + ida.y; u.y = silu_f(z);
            z = (acc[mf][nf][2] + bsb) * invb + bbb + idb.x; v.x = silu_f(z);
            z = (acc[mf][nf][3] + bsb) * invb + bbb + idb.y; v.y = silu_f(z);
            *(float2*)(out + ra + off) = u;
            *(float2*)(out + rb + off) = v;
        }
    }
}

// ---------------------------------------------------------------------------
extern "C" void kernel_launch(void* const* d_in, const int* in_sizes, int n_in,
                              void* d_out, int out_size)
{
    const float* x     = (const float*)d_in[0];
    const float* wconv = (const float*)d_in[1];
    const float* w1    = (const float*)d_in[2];
    const float* b1    = (const float*)d_in[3];
    const float* gamma = (const float*)d_in[4];
    const float* beta  = (const float*)d_in[5];
    const float* mean  = (const float*)d_in[6];
    const float* var   = (const float*)d_in[7];
    float* out = (float*)d_out;

    static bool attr_done = false;
    if (!attr_done) {
        cudaFuncSetAttribute(k_conv3, cudaFuncAttributeMaxDynamicSharedMemorySize, DSMEM_BYTES);
        cudaFuncSetAttribute(k_pw,    cudaFuncAttributeMaxDynamicSharedMemorySize, DSMEM_BYTES);
        attr_done = true;
    }

    k_repack_conv<<<(C2 * C1 * 9 + 255) / 256, 256>>>(wconv);
    k_repack_pw  <<<(C2 * C2 + 255) / 256, 256>>>(w1);

    dim3 grid(H_ / 2, 2, B_);   // 64 row-pairs x 2 oc-halves x 16 batch
    k_conv3<<<grid, 256, DSMEM_BYTES>>>(x, gamma, beta, mean, var);
    k_pw   <<<grid, 256, DSMEM_BYTES>>>(b1, gamma, beta, mean, var, out);
}

// round 5
// speedup vs baseline: 8.9632x; 1.2187x over previous
#include <cuda_runtime.h>
#include <cuda_fp16.h>

// SConv via mma.sync m16n8k16 fp16 (R4).
// conv3x3+BN+SiLU -> g_y(f32)+g_yh(f16) ; shift+conv1x1+bias+BN+id+SiLU -> out
// B=16, C1=128, C2=256, H=W=128.
// Implicit GEMM, CTA tile 128oc x 256px (2 rows), 8 warps (2Mx4N), warp 64x64.
// fp16 operands (same 10-bit mantissa as tf32), fp32 accumulate.

#define B_  16
#define C1  128
#define C2  256
#define H_  128
#define W_  128
#define HW  (H_*W_)
#define EPSBN 1e-5f

typedef unsigned int uint;

__device__ float  g_y [(size_t)B_ * C2 * H_ * W_];   // identity, fp32
__device__ __half g_yh[(size_t)B_ * C2 * H_ * W_];   // y in fp16 (pw B operand)
__device__ __half g_xh[(size_t)B_ * C1 * H_ * W_];   // x in fp16
__device__ __half g_wA16[36 * 2 * 4096];             // conv w, frag order
__device__ __half g_wB16[ 8 * 2 * 4096];             // 1x1 w, frag order

__device__ __forceinline__ float silu_f(float v) { return v / (1.0f + __expf(-v)); }
__device__ __forceinline__ uint smem_u32(const void* p) {
    uint a;
    asm("{ .reg .u64 t; cvta.to.shared.u64 t, %1; cvt.u32.u64 %0, t; }" : "=r"(a) : "l"(p));
    return a;
}

#define MMA16(d, a, b) \
    asm volatile("mma.sync.aligned.m16n8k16.row.col.f32.f16.f16.f32 " \
        "{%0,%1,%2,%3}, {%4,%5,%6,%7}, {%8,%9}, {%0,%1,%2,%3};" \
        : "+f"((d)[0]), "+f"((d)[1]), "+f"((d)[2]), "+f"((d)[3]) \
        : "r"((a).x), "r"((a).y), "r"((a).z), "r"((a).w), "r"((b).x), "r"((b).y))

#define CP_ASYNC16(sm, gp) \
    asm volatile("cp.async.cg.shared.global [%0], [%1], 16;" :: "r"(sm), "l"(gp))
#define CP_COMMIT() asm volatile("cp.async.commit_group;")
#define CP_WAIT0()  asm volatile("cp.async.wait_group 0;" ::: "memory")

// ---------------------------------------------------------------- layouts --
// A chunk tile [M=128][K=32] fp16, frag order, 8192 B:
//   halfword idx = ((kstep*8+mblock)*32 + lane)*8 + reg*2 + half
//   kstep=kk>>4, mblock=m>>4, lane=((m&7)<<2)|((kk>>1)&3),
//   reg=((kk>>3)&1)*2+((m>>3)&1), half=kk&1
// B chunk tile [K=32][N=256] fp16: rows (kstep*32+nblock), 264B stride (8B pad):
//   byte = (kstep*32+nblock)*264 + (((n&7)<<2)|((kk>>1)&3))*8 + ((kk>>3)&1)*4 + (kk&1)*2
#define ROWB 264
#define A_BYTES 8192
#define B_BYTES (64 * ROWB)          // 16896
#define STAGE  (A_BYTES + B_BYTES)
#define DSMEM_BYTES (2 * STAGE)      // 50176

// --------------------------------------------------------- repack kernels --
__global__ __launch_bounds__(256) void k_repack_conv(const float* __restrict__ wc) {
    int idx = blockIdx.x * 256 + threadIdx.x;
    if (idx >= C2 * C1 * 9) return;
    int tap = idx % 9, rest = idx / 9;
    int ic = rest % C1, oc = rest / C1;
    int it = (ic >> 5) * 9 + tap;
    int kk = ic & 31, m = oc & 127, ocg = oc >> 7;
    int off = (((kk >> 4) * 8 + (m >> 4)) * 32 + (((m & 7) << 2) | ((kk >> 1) & 3))) * 8
            + (((kk >> 3) & 1) * 2 + ((m >> 3) & 1)) * 2 + (kk & 1);
    g_wA16[(size_t)(it * 2 + ocg) * 4096 + off] = __float2half_rn(wc[idx]);
}
__global__ __launch_bounds__(256) void k_repack_pw(const float* __restrict__ w1) {
    int idx = blockIdx.x * 256 + threadIdx.x;
    if (idx >= C2 * C2) return;
    int ic = idx % C2, oc = idx / C2;
    int kc = ic >> 5;
    int kk = ic & 31, m = oc & 127, ocg = oc >> 7;
    int off = (((kk >> 4) * 8 + (m >> 4)) * 32 + (((m & 7) << 2) | ((kk >> 1) & 3))) * 8
            + (((kk >> 3) & 1) * 2 + ((m >> 3) & 1)) * 2 + (kk & 1);
    g_wB16[(size_t)(kc * 2 + ocg) * 4096 + off] = __float2half_rn(w1[idx]);
}
__global__ __launch_bounds__(256) void k_cvt_x(const float* __restrict__ x) {
    size_t i = (size_t)blockIdx.x * 256 + threadIdx.x;   // over 8.39M float4
    float4 v = __ldg((const float4*)x + i);
    __half2* d = (__half2*)g_xh;
    d[2 * i]     = __floats2half2_rn(v.x, v.y);
    d[2 * i + 1] = __floats2half2_rn(v.z, v.w);
}

// ------------------------------------------------------------ B staging ---
struct BReg { uint e[8], o[8]; };

__device__ __forceinline__ void gather_ldg(BReg& r, const __half* srcE, bool valid) {
    if (valid) {
        const uint4* pe = (const uint4*)srcE;
        const uint4* po = (const uint4*)(srcE + HW);
        uint4 a = __ldg(pe), b = __ldg(pe + 1);
        uint4 c = __ldg(po), d = __ldg(po + 1);
        r.e[0]=a.x; r.e[1]=a.y; r.e[2]=a.z; r.e[3]=a.w;
        r.e[4]=b.x; r.e[5]=b.y; r.e[6]=b.z; r.e[7]=b.w;
        r.o[0]=c.x; r.o[1]=c.y; r.o[2]=c.z; r.o[3]=c.w;
        r.o[4]=d.x; r.o[5]=d.y; r.o[6]=d.z; r.o[7]=d.w;
    } else {
#pragma unroll
        for (int i = 0; i < 8; ++i) { r.e[i] = 0u; r.o[i] = 0u; }
    }
}

// STS with shift ss applied in the destination index; edge cols zero-filled.
__device__ __forceinline__ void gather_sts(char* Bbuf, const BReg& r,
                                           int rowsel, int w0, int ss, int kkp) {
    char* base = Bbuf + (kkp >> 3) * (32 * ROWB) + ((kkp >> 2) & 1) * 4;
    const int laneb = kkp & 3;
    if (ss == 1 && w0 == 0) {
        int n = rowsel * 128;
        *(uint*)(base + (n >> 3) * ROWB + (((n & 7) << 2) | laneb) * 8) = 0u;
    }
    if (ss == -1 && w0 == 112) {
        int n = rowsel * 128 + 127;
        *(uint*)(base + (n >> 3) * ROWB + (((n & 7) << 2) | laneb) * 8) = 0u;
    }
#pragma unroll
    for (int q = 0; q < 16; ++q) {
        int nw = w0 + q + ss;
        if (nw < 0 || nw > 127) continue;
        uint word = __byte_perm(r.e[q >> 1], r.o[q >> 1], (q & 1) ? 0x7632u : 0x5410u);
        int n = rowsel * 128 + nw;
        *(uint*)(base + (n >> 3) * ROWB + (((n & 7) << 2) | laneb) * 8) = word;
    }
}

__device__ __forceinline__ void stageA_async(uint Asm, const __half* src, int tid) {
    const char* g = (const char*)src;
    CP_ASYNC16(Asm + tid * 16,        g + tid * 16);
    CP_ASYNC16(Asm + 4096 + tid * 16, g + 4096 + tid * 16);
}

// ----------------------------------------------------------------- MMA ---
__device__ __forceinline__ void mma_chunk16(const char* Ab, const char* Bb,
                                            int wm, int wn, int lane,
                                            float acc[4][8][4]) {
#pragma unroll
    for (int ks = 0; ks < 2; ++ks) {
        uint4 a[4];
#pragma unroll
        for (int mf = 0; mf < 4; ++mf)
            a[mf] = *(const uint4*)(Ab + (((ks * 8 + wm * 4 + mf) * 32 + lane) << 4));
        uint2 bf[8];
#pragma unroll
        for (int nf = 0; nf < 8; ++nf)
            bf[nf] = *(const uint2*)(Bb + (ks * 32 + wn * 8 + nf) * ROWB + lane * 8);
#pragma unroll
        for (int mf = 0; mf < 4; ++mf)
#pragma unroll
            for (int nf = 0; nf < 8; ++nf)
                MMA16(acc[mf][nf], a[mf], bf[nf]);
    }
}

// ------------------------------------------------------ conv3x3 + BN + SiLU
__global__ __launch_bounds__(256, 1) void k_conv3(
    const float* __restrict__ gamma, const float* __restrict__ beta,
    const float* __restrict__ mean,  const float* __restrict__ var)
{
    extern __shared__ __align__(16) char dsm[];
    char* A0 = dsm;          char* Bb0 = dsm + A_BYTES;
    char* A1 = dsm + STAGE;  char* Bb1 = dsm + STAGE + A_BYTES;
    const uint Asm0 = smem_u32(A0), Asm1 = smem_u32(A1);

    const int tid = threadIdx.x;
    const int wrp = tid >> 5, lane = tid & 31;
    const int wm = wrp >> 2, wn = wrp & 3;
    const int kkp = tid >> 4, j = tid & 15;
    const int rowsel = j >> 3, w0 = (j & 7) * 16;
    const int h0  = blockIdx.x * 2;
    const int ocg = blockIdx.y, oc0 = ocg * 128;
    const int b   = blockIdx.z;

    const __half* xh = g_xh + (size_t)b * C1 * HW;

    float acc[4][8][4];
#pragma unroll
    for (int i = 0; i < 4; ++i)
#pragma unroll
        for (int jj = 0; jj < 8; ++jj)
#pragma unroll
            for (int q = 0; q < 4; ++q) acc[i][jj][q] = 0.0f;

    BReg br;
    int ssN = 0;  // shift of the staged chunk
    // prologue: chunk 0 (kc=0, tap=0: ky=0, kx=0 -> ss=+1, hs=h0+rowsel-1)
    {
        stageA_async(Asm0, g_wA16 + (size_t)(0 * 2 + ocg) * 4096, tid);
        CP_COMMIT();
        int hs = h0 + rowsel - 1;
        bool valid = (uint)hs < (uint)H_;
        ssN = 1;
        gather_ldg(br, xh + (size_t)(2 * kkp) * HW + hs * W_ + w0, valid);
        CP_WAIT0();
        gather_sts(Bb0, br, rowsel, w0, ssN, kkp);
    }
    __syncthreads();

#pragma unroll 1
    for (int it = 0; it < 36; ++it) {
        const int cur = it & 1;
        const bool pf = (it + 1) < 36;
        if (pf) {
            const int nit = it + 1;
            const int kc = nit / 9, tap = nit - kc * 9;
            const int ky = tap / 3, kx = tap - ky * 3;
            stageA_async(cur ? Asm0 : Asm1,
                         g_wA16 + (size_t)(nit * 2 + ocg) * 4096, tid);
            CP_COMMIT();
            int hs = h0 + rowsel + ky - 1;
            bool valid = (uint)hs < (uint)H_;
            ssN = 1 - kx;
            gather_ldg(br, xh + (size_t)(kc * 32 + 2 * kkp) * HW + hs * W_ + w0, valid);
        }
        mma_chunk16(cur ? A1 : A0, cur ? Bb1 : Bb0, wm, wn, lane, acc);
        if (pf) {
            gather_sts(cur ? Bb0 : Bb1, br, rowsel, w0, ssN, kkp);
            CP_WAIT0();
        }
        __syncthreads();
    }

    // epilogue: BN + SiLU -> g_y (f32) + g_yh (f16)
#pragma unroll
    for (int mf = 0; mf < 4; ++mf) {
        const int m0 = wm * 64 + mf * 16 + (lane >> 2);
        const int oc_a = oc0 + m0, oc_b = oc_a + 8;
        const float inva = __ldg(&gamma[oc_a]) * rsqrtf(__ldg(&var[oc_a]) + EPSBN);
        const float bba  = __ldg(&beta[oc_a]) - __ldg(&mean[oc_a]) * inva;
        const float invb = __ldg(&gamma[oc_b]) * rsqrtf(__ldg(&var[oc_b]) + EPSBN);
        const float bbb  = __ldg(&beta[oc_b]) - __ldg(&mean[oc_b]) * invb;
        const size_t ra = ((size_t)b * C2 + oc_a) * HW;
        const size_t rb = ((size_t)b * C2 + oc_b) * HW;
#pragma unroll
        for (int nf = 0; nf < 8; ++nf) {
            const int n = wn * 64 + nf * 8 + (lane & 3) * 2;
            const int off = (h0 + (n >> 7)) * W_ + (n & 127);
            float2 u, v;
            u.x = silu_f(acc[mf][nf][0] * inva + bba);
            u.y = silu_f(acc[mf][nf][1] * inva + bba);
            v.x = silu_f(acc[mf][nf][2] * invb + bbb);
            v.y = silu_f(acc[mf][nf][3] * invb + bbb);
            *(float2*)(g_y + ra + off) = u;
            *(float2*)(g_y + rb + off) = v;
            *(__half2*)(g_yh + ra + off) = __floats2half2_rn(u.x, u.y);
            *(__half2*)(g_yh + rb + off) = __floats2half2_rn(v.x, v.y);
        }
    }
}

// --------------------------- shift + conv1x1 + bias + BN + identity + SiLU
__global__ __launch_bounds__(256, 1) void k_pw(
    const float* __restrict__ b1,
    const float* __restrict__ gamma, const float* __restrict__ beta,
    const float* __restrict__ mean,  const float* __restrict__ var,
    float* __restrict__ out)
{
    extern __shared__ __align__(16) char dsm[];
    char* A0 = dsm;          char* Bb0 = dsm + A_BYTES;
    char* A1 = dsm + STAGE;  char* Bb1 = dsm + STAGE + A_BYTES;
    const uint Asm0 = smem_u32(A0), Asm1 = smem_u32(A1);

    const int tid = threadIdx.x;
    const int wrp = tid >> 5, lane = tid & 31;
    const int wm = wrp >> 2, wn = wrp & 3;
    const int kkp = tid >> 4, j = tid & 15;
    const int rowsel = j >> 3, w0 = (j & 7) * 16;
    const int h0  = blockIdx.x * 2;
    const int ocg = blockIdx.y, oc0 = ocg * 128;
    const int b   = blockIdx.z;

    const __half* yh = g_yh + (size_t)b * C2 * HW;

    float acc[4][8][4];
#pragma unroll
    for (int i = 0; i < 4; ++i)
#pragma unroll
        for (int jj = 0; jj < 8; ++jj)
#pragma unroll
            for (int q = 0; q < 4; ++q) acc[i][jj][q] = 0.0f;

    // per-chunk shift params: grp = kc>>1
    BReg br;
    int ssN = 0;
    {
        // chunk 0: grp0 -> ss=+1, same row
        stageA_async(Asm0, g_wB16 + (size_t)(0 * 2 + ocg) * 4096, tid);
        CP_COMMIT();
        ssN = 1;
        gather_ldg(br, yh + (size_t)(2 * kkp) * HW + (h0 + rowsel) * W_ + w0, true);
        CP_WAIT0();
        gather_sts(Bb0, br, rowsel, w0, ssN, kkp);
    }
    __syncthreads();

#pragma unroll 1
    for (int it = 0; it < 8; ++it) {
        const int cur = it & 1;
        const bool pf = (it + 1) < 8;
        if (pf) {
            const int kc = it + 1, grp = kc >> 1;
            stageA_async(cur ? Asm0 : Asm1,
                         g_wB16 + (size_t)(kc * 2 + ocg) * 4096, tid);
            CP_COMMIT();
            int hs = h0 + rowsel;
            bool valid = true;
            if      (grp == 0) ssN = 1;
            else if (grp == 1) { ssN = 0; hs += 1; valid = hs < H_; }
            else if (grp == 2) ssN = -1;
            else               { ssN = 0; hs -= 1; valid = hs >= 0; }
            gather_ldg(br, yh + (size_t)(kc * 32 + 2 * kkp) * HW + hs * W_ + w0, valid);
        }
        mma_chunk16(cur ? A1 : A0, cur ? Bb1 : Bb0, wm, wn, lane, acc);
        if (pf) {
            gather_sts(cur ? Bb0 : Bb1, br, rowsel, w0, ssN, kkp);
            CP_WAIT0();
        }
        __syncthreads();
    }

    // epilogue: +bias, BN, +identity, SiLU -> out
#pragma unroll
    for (int mf = 0; mf < 4; ++mf) {
        const int m0 = wm * 64 + mf * 16 + (lane >> 2);
        const int oc_a = oc0 + m0, oc_b = oc_a + 8;
        const float inva = __ldg(&gamma[oc_a]) * rsqrtf(__ldg(&var[oc_a]) + EPSBN);
        const float bba  = __ldg(&beta[oc_a]) - __ldg(&mean[oc_a]) * inva;
        const float bsa  = __ldg(&b1[oc_a]);
        const float invb = __ldg(&gamma[oc_b]) * rsqrtf(__ldg(&var[oc_b]) + EPSBN);
        const float bbb  = __ldg(&beta[oc_b]) - __ldg(&mean[oc_b]) * invb;
        const float bsb  = __ldg(&b1[oc_b]);
        const size_t ra = ((size_t)b * C2 + oc_a) * HW;
        const size_t rb = ((size_t)b * C2 + oc_b) * HW;
#pragma unroll
        for (int nf = 0; nf < 8; ++nf) {
            const int n = wn * 64 + nf * 8 + (lane & 3) * 2;
            const int off = (h0 + (n >> 7)) * W_ + (n & 127);
            float2 ida = *(const float2*)(g_y + ra + off);
            float2 idb = *(const float2*)(g_y + rb + off);
            float2 u, v; float z;
            z = (acc[mf][nf][0] + bsa) * inva + bba + ida.x; u.x = silu_f(z);
            z = (acc[mf][nf][1] + bsa) * inva + bba + ida.y; u.y = silu_f(z);
            z = (acc[mf][nf][2] + bsb) * invb + bbb + idb.x; v.x = silu_f(z);
            z = (acc[mf][nf][3] + bsb) * invb + bbb + idb.y; v.y = silu_f(z);
            *(float2*)(out + ra + off) = u;
            *(float2*)(out + rb + off) = v;
        }
    }
}

// ---------------------------------------------------------------------------
extern "C" void kernel_launch(void* const* d_in, const int* in_sizes, int n_in,
                              void* d_out, int out_size)
{
    const float* x     = (const float*)d_in[0];
    const float* wconv = (const float*)d_in[1];
    const float* w1    = (const float*)d_in[2];
    const float* b1    = (const float*)d_in[3];
    const float* gamma = (const float*)d_in[4];
    const float* beta  = (const float*)d_in[5];
    const float* mean  = (const float*)d_in[6];
    const float* var   = (const float*)d_in[7];
    float* out = (float*)d_out;

    static bool attr_done = false;
    if (!attr_done) {
        cudaFuncSetAttribute(k_conv3, cudaFuncAttributeMaxDynamicSharedMemorySize, DSMEM_BYTES);
        cudaFuncSetAttribute(k_pw,    cudaFuncAttributeMaxDynamicSharedMemorySize, DSMEM_BYTES);
        attr_done = true;
    }

    k_repack_conv<<<(C2 * C1 * 9 + 255) / 256, 256>>>(wconv);
    k_repack_pw  <<<(C2 * C2 + 255) / 256, 256>>>(w1);
    k_cvt_x      <<<((size_t)B_ * C1 * HW / 4 + 255) / 256, 256>>>(x);

    dim3 grid(H_ / 2, 2, B_);
    k_conv3<<<grid, 256, DSMEM_BYTES>>>(gamma, beta, mean, var);
    k_pw   <<<grid, 256, DSMEM_BYTES>>>(b1, gamma, beta, mean, var, out);
}

// round 6
// speedup vs baseline: 12.3042x; 1.3727x over previous
#include <cuda_runtime.h>
#include <cuda_fp16.h>

// SConv R5: pure cp.async implicit-GEMM pipelines (mma.sync m16n8k16 fp16).
// All shifts pre-applied in global memory:
//   - x pre-converted to fp16 in 3 column-shift variants (conv taps).
//   - conv epilogue writes y pre-shifted per channel group (pw B operand).
// B tiles: row-major [k][n] + XOR swizzle, fragments via ldmatrix.x4.trans.
// 3-stage cp.async pipeline. CTA 128oc x 256px, 8 warps 2Mx4N, warp 64x64.

#define B_  16
#define C1  128
#define C2  256
#define H_  128
#define W_  128
#define HW  (H_*W_)
#define EPSBN 1e-5f

typedef unsigned int uint;

#define XVSZ ((size_t)B_ * C1 * HW)

__device__ __half g_xv [3 * XVSZ];                // x fp16, col-shift variants -1/0/+1
__device__ __half g_yi [(size_t)B_ * C2 * HW];    // y fp16 plain (identity)
__device__ __half g_ysh[(size_t)B_ * C2 * HW];    // y fp16 pre-shifted per group
__device__ __half g_wA16[36 * 2 * 4096];          // conv w, frag order
__device__ __half g_wB16[ 8 * 2 * 4096];          // 1x1 w, frag order

__device__ __forceinline__ float silu_f(float v) { return v / (1.0f + __expf(-v)); }
__device__ __forceinline__ uint smem_u32(const void* p) {
    uint a;
    asm("{ .reg .u64 t; cvta.to.shared.u64 t, %1; cvt.u32.u64 %0, t; }" : "=r"(a) : "l"(p));
    return a;
}

#define MMA16(d, a, b0v, b1v) \
    asm volatile("mma.sync.aligned.m16n8k16.row.col.f32.f16.f16.f32 " \
        "{%0,%1,%2,%3}, {%4,%5,%6,%7}, {%8,%9}, {%0,%1,%2,%3};" \
        : "+f"((d)[0]), "+f"((d)[1]), "+f"((d)[2]), "+f"((d)[3]) \
        : "r"((a).x), "r"((a).y), "r"((a).z), "r"((a).w), "r"(b0v), "r"(b1v))

#define CP_A16(sm, gp) \
    asm volatile("cp.async.cg.shared.global [%0], [%1], 16;" :: "r"(sm), "l"(gp))
#define CP_A16Z(sm, gp, sz) \
    asm volatile("cp.async.cg.shared.global [%0], [%1], 16, %2;" :: "r"(sm), "l"(gp), "r"(sz))
#define CP_COMMIT() asm volatile("cp.async.commit_group;")
#define CP_WAIT1()  asm volatile("cp.async.wait_group 1;" ::: "memory")
#define CP_WAIT0()  asm volatile("cp.async.wait_group 0;" ::: "memory")

// Stage layout: A 8192 B (frag order) + B 16384 B (row-major [kk][n], 512B rows,
// 16B-granule XOR swizzle: granule (kk,g) at kk*512 + ((g^(kk&7))<<4)).
#define A_BYTES 8192
#define B_BYTES 16384
#define STAGE   (A_BYTES + B_BYTES)
#define NSTG    3
#define DSMEM_BYTES (NSTG * STAGE)   // 73728

// --------------------------------------------------------- repack kernels --
// A frag layout (verified R4): halfword idx =
//  ((kk>>4)*8 + (m>>4))*256 + (((m&7)<<2)|((kk>>1)&3))*8 + (((kk>>3)&1)*2+((m>>3)&1))*2 + (kk&1)
__device__ __forceinline__ int fragoff(int m, int kk) {
    return (((kk >> 4) * 8 + (m >> 4)) * 32 + (((m & 7) << 2) | ((kk >> 1) & 3))) * 8
         + (((kk >> 3) & 1) * 2 + ((m >> 3) & 1)) * 2 + (kk & 1);
}
__global__ __launch_bounds__(256) void k_repack_conv(const float* __restrict__ wc) {
    int idx = blockIdx.x * 256 + threadIdx.x;
    if (idx >= C2 * C1 * 9) return;
    int tap = idx % 9, rest = idx / 9;
    int ic = rest % C1, oc = rest / C1;
    int it = (ic >> 5) * 9 + tap;
    g_wA16[(size_t)(it * 2 + (oc >> 7)) * 4096 + fragoff(oc & 127, ic & 31)] =
        __float2half_rn(wc[idx]);
}
__global__ __launch_bounds__(256) void k_repack_pw(const float* __restrict__ w1) {
    int idx = blockIdx.x * 256 + threadIdx.x;
    if (idx >= C2 * C2) return;
    int ic = idx % C2, oc = idx / C2;
    g_wB16[(size_t)((ic >> 5) * 2 + (oc >> 7)) * 4096 + fragoff(oc & 127, ic & 31)] =
        __float2half_rn(w1[idx]);
}

// x -> 3 fp16 column-shift variants
__global__ __launch_bounds__(256) void k_prep_x(const float* __restrict__ x) {
    size_t i = (size_t)blockIdx.x * 256 + threadIdx.x;   // over XVSZ/8
    size_t base = i * 8;
    int w0 = (int)(base & 127);
    const float* p = x + base;
    float4 a  = __ldg((const float4*)p);
    float4 b4 = __ldg((const float4*)(p + 4));
    float xm1 = (w0 > 0)   ? __ldg(p - 1) : 0.f;
    float xp8 = (w0 < 120) ? __ldg(p + 8) : 0.f;
    __half2* v0 = (__half2*)g_xv + i * 4;
    __half2* v1 = (__half2*)(g_xv + XVSZ) + i * 4;
    __half2* v2 = (__half2*)(g_xv + 2 * XVSZ) + i * 4;
    v1[0] = __floats2half2_rn(a.x, a.y);  v1[1] = __floats2half2_rn(a.z, a.w);
    v1[2] = __floats2half2_rn(b4.x, b4.y); v1[3] = __floats2half2_rn(b4.z, b4.w);
    v0[0] = __floats2half2_rn(xm1, a.x);  v0[1] = __floats2half2_rn(a.y, a.z);
    v0[2] = __floats2half2_rn(a.w, b4.x); v0[3] = __floats2half2_rn(b4.y, b4.z);
    v2[0] = __floats2half2_rn(a.y, a.z);  v2[1] = __floats2half2_rn(a.w, b4.x);
    v2[2] = __floats2half2_rn(b4.y, b4.z); v2[3] = __floats2half2_rn(b4.w, xp8);
}

// zero the never-written border strips of g_ysh
__global__ __launch_bounds__(256) void k_zero_sh() {
    int idx = blockIdx.x * 256 + threadIdx.x;   // 4*16*64*128 = 524288
    if (idx >= 4 * 16 * 64 * 128) return;
    int grp = idx >> 17, r = idx & 131071;
    int b = r >> 13, r2 = r & 8191;
    int c = r2 >> 7, p = r2 & 127;
    int oc, h, w;
    if      (grp == 0) { oc = c;       h = p;   w = 0;   }
    else if (grp == 1) { oc = 64 + c;  h = 127; w = p;   }
    else if (grp == 2) { oc = 128 + c; h = p;   w = 127; }
    else               { oc = 192 + c; h = 0;   w = p;   }
    g_ysh[(((size_t)b * C2 + oc) << 14) + h * W_ + w] = __float2half_rn(0.f);
}

// --------------------------------------------------------- staging helpers --
__device__ __forceinline__ void cp_issue_A(uint Asm, const __half* src, int tid) {
    const char* g = (const char*)src;
    CP_A16(Asm + tid * 16, g + tid * 16);
    CP_A16(Asm + 4096 + tid * 16, g + 4096 + tid * 16);
}
// B: thread owns granule column g (=tid&31) and rows kk0+8i (kk0=tid>>5).
__device__ __forceinline__ void cp_issue_B(uint Bsm, const __half* vbase,
                                           int kk0, uint gxor, int hs, int wcol) {
    uint ok = ((uint)hs < 128u) ? 16u : 0u;
    int hsc = (hs < 0) ? 0 : (hs > 127 ? 127 : hs);
    const char* s = (const char*)(vbase + (size_t)kk0 * HW + hsc * W_ + wcol);
    uint d = Bsm + kk0 * 512 + gxor;
#pragma unroll
    for (int i = 0; i < 4; ++i)
        CP_A16Z(d + i * (8 * 512), s + (size_t)i * 8 * HW * 2, ok);
}

// ----------------------------------------------------------------- MMA -----
__device__ __forceinline__ void mma_chunk(uint Asm, uint Bsm, int wm, int wn,
                                          int lane, float acc[4][8][4]) {
    const int j = lane >> 3, r = lane & 7;
    const int jk = (j & 1) << 3, jn = j >> 1;
#pragma unroll
    for (int ks = 0; ks < 2; ++ks) {
        uint4 a[4];
#pragma unroll
        for (int mf = 0; mf < 4; ++mf) {
            uint ad = Asm + (((ks * 8 + wm * 4 + mf) * 32 + lane) << 4);
            asm volatile("ld.shared.v4.b32 {%0,%1,%2,%3}, [%4];"
                : "=r"(a[mf].x), "=r"(a[mf].y), "=r"(a[mf].z), "=r"(a[mf].w) : "r"(ad));
        }
        uint bf[8][2];
#pragma unroll
        for (int p = 0; p < 4; ++p) {
            int krow = ks * 16 + jk + r;
            int oct  = wn * 8 + 2 * p + jn;
            uint ad = Bsm + krow * 512 + ((uint)(oct ^ (krow & 7)) << 4);
            uint d0, d1, d2, d3;
            asm volatile("ldmatrix.sync.aligned.m8n8.x4.trans.shared.b16 "
                "{%0,%1,%2,%3}, [%4];"
                : "=r"(d0), "=r"(d1), "=r"(d2), "=r"(d3) : "r"(ad));
            bf[2 * p][0] = d0; bf[2 * p][1] = d1;
            bf[2 * p + 1][0] = d2; bf[2 * p + 1][1] = d3;
        }
#pragma unroll
        for (int mf = 0; mf < 4; ++mf)
#pragma unroll
            for (int nf = 0; nf < 8; ++nf)
                MMA16(acc[mf][nf], a[mf], bf[nf][0], bf[nf][1]);
    }
}

// ------------------------------------------------------ conv3x3 + BN + SiLU
__global__ __launch_bounds__(256, 1) void k_conv3(
    const float* __restrict__ gamma, const float* __restrict__ beta,
    const float* __restrict__ mean,  const float* __restrict__ var)
{
    extern __shared__ __align__(16) char dsm[];
    const uint smb = smem_u32(dsm);

    const int tid = threadIdx.x;
    const int wrp = tid >> 5, lane = tid & 31;
    const int wm = wrp >> 2, wn = wrp & 3;
    const int kk0 = tid >> 5, g = tid & 31;
    const int rowsel = g >> 4, wcol = (g & 15) * 8;
    const uint gxor = ((uint)(g ^ (kk0 & 7))) << 4;
    const int h0  = blockIdx.x * 2;
    const int ocg = blockIdx.y, oc0 = ocg * 128;
    const int b   = blockIdx.z;

    float acc[4][8][4];
#pragma unroll
    for (int i = 0; i < 4; ++i)
#pragma unroll
        for (int jj = 0; jj < 8; ++jj)
#pragma unroll
            for (int q = 0; q < 4; ++q) acc[i][jj][q] = 0.0f;

    const size_t bofs = (size_t)b * C1 * HW;
#define ISSUE_CONV(nit, s) do { \
        int kc_ = (nit) / 9, tap_ = (nit) - 9 * kc_; \
        int ky_ = tap_ / 3, kx_ = tap_ - 3 * ky_; \
        cp_issue_A(smb + (s) * STAGE, g_wA16 + (size_t)((nit) * 2 + ocg) * 4096, tid); \
        const __half* vb_ = g_xv + (size_t)kx_ * XVSZ + bofs + (size_t)kc_ * 32 * HW; \
        cp_issue_B(smb + (s) * STAGE + A_BYTES, vb_, kk0, gxor, h0 + rowsel + ky_ - 1, wcol); \
        CP_COMMIT(); \
    } while (0)

    ISSUE_CONV(0, 0);
    ISSUE_CONV(1, 1);

#pragma unroll 1
    for (int it = 0; it < 36; ++it) {
        if (it + 2 < 36) CP_WAIT1(); else CP_WAIT0();
        __syncthreads();
        if (it + 2 < 36) {
            int s = (it + 2) % NSTG;
            ISSUE_CONV(it + 2, s);
        }
        int cs = it % NSTG;
        mma_chunk(smb + cs * STAGE, smb + cs * STAGE + A_BYTES, wm, wn, lane, acc);
    }
#undef ISSUE_CONV

    // epilogue: BN + SiLU -> g_yi (plain) + g_ysh (shifted by group)
    const int grp = (ocg * 2 + wm) & 3;   // warp-uniform
#pragma unroll
    for (int mf = 0; mf < 4; ++mf) {
        const int oc_a = oc0 + wm * 64 + mf * 16 + (lane >> 2);
        const int oc_b = oc_a + 8;
        const float inva = __ldg(&gamma[oc_a]) * rsqrtf(__ldg(&var[oc_a]) + EPSBN);
        const float bba  = __ldg(&beta[oc_a]) - __ldg(&mean[oc_a]) * inva;
        const float invb = __ldg(&gamma[oc_b]) * rsqrtf(__ldg(&var[oc_b]) + EPSBN);
        const float bbb  = __ldg(&beta[oc_b]) - __ldg(&mean[oc_b]) * invb;
        const size_t ra = ((size_t)b * C2 + oc_a) * HW;
        const size_t rb = ((size_t)b * C2 + oc_b) * HW;
#pragma unroll
        for (int nf = 0; nf < 8; ++nf) {
            const int n = wn * 64 + nf * 8 + (lane & 3) * 2;
            const int h = h0 + (n >> 7), w = n & 127;
            const int off = h * W_ + w;
            float2 u, v;
            u.x = silu_f(acc[mf][nf][0] * inva + bba);
            u.y = silu_f(acc[mf][nf][1] * inva + bba);
            v.x = silu_f(acc[mf][nf][2] * invb + bbb);
            v.y = silu_f(acc[mf][nf][3] * invb + bbb);
            __half2 uh = __floats2half2_rn(u.x, u.y);
            __half2 vh = __floats2half2_rn(v.x, v.y);
            *(__half2*)(g_yi + ra + off) = uh;
            *(__half2*)(g_yi + rb + off) = vh;
            if (grp == 0) {            // dest (h, w+1): z[w'] = y[w'-1]
                g_ysh[ra + off + 1] = __low2half(uh);
                g_ysh[rb + off + 1] = __low2half(vh);
                if (w < 126) {
                    g_ysh[ra + off + 2] = __high2half(uh);
                    g_ysh[rb + off + 2] = __high2half(vh);
                }
            } else if (grp == 1) {     // dest (h-1, w)
                if (h > 0) {
                    *(__half2*)(g_ysh + ra + off - W_) = uh;
                    *(__half2*)(g_ysh + rb + off - W_) = vh;
                }
            } else if (grp == 2) {     // dest (h, w-1)
                if (w > 0) {
                    g_ysh[ra + off - 1] = __low2half(uh);
                    g_ysh[rb + off - 1] = __low2half(vh);
                }
                g_ysh[ra + off] = __high2half(uh);
                g_ysh[rb + off] = __high2half(vh);
            } else {                   // dest (h+1, w)
                if (h < 127) {
                    *(__half2*)(g_ysh + ra + off + W_) = uh;
                    *(__half2*)(g_ysh + rb + off + W_) = vh;
                }
            }
        }
    }
}

// --------------------------- conv1x1(shifted y) + bias + BN + id + SiLU ----
__global__ __launch_bounds__(256, 1) void k_pw(
    const float* __restrict__ b1,
    const float* __restrict__ gamma, const float* __restrict__ beta,
    const float* __restrict__ mean,  const float* __restrict__ var,
    float* __restrict__ out)
{
    extern __shared__ __align__(16) char dsm[];
    const uint smb = smem_u32(dsm);

    const int tid = threadIdx.x;
    const int wrp = tid >> 5, lane = tid & 31;
    const int wm = wrp >> 2, wn = wrp & 3;
    const int kk0 = tid >> 5, g = tid & 31;
    const int rowsel = g >> 4, wcol = (g & 15) * 8;
    const uint gxor = ((uint)(g ^ (kk0 & 7))) << 4;
    const int h0  = blockIdx.x * 2;
    const int ocg = blockIdx.y, oc0 = ocg * 128;
    const int b   = blockIdx.z;

    float acc[4][8][4];
#pragma unroll
    for (int i = 0; i < 4; ++i)
#pragma unroll
        for (int jj = 0; jj < 8; ++jj)
#pragma unroll
            for (int q = 0; q < 4; ++q) acc[i][jj][q] = 0.0f;

    const size_t bofs = (size_t)b * C2 * HW;
#define ISSUE_PW(nit, s) do { \
        cp_issue_A(smb + (s) * STAGE, g_wB16 + (size_t)((nit) * 2 + ocg) * 4096, tid); \
        const __half* vb_ = g_ysh + bofs + (size_t)(nit) * 32 * HW; \
        cp_issue_B(smb + (s) * STAGE + A_BYTES, vb_, kk0, gxor, h0 + rowsel, wcol); \
        CP_COMMIT(); \
    } while (0)

    ISSUE_PW(0, 0);
    ISSUE_PW(1, 1);

#pragma unroll 1
    for (int it = 0; it < 8; ++it) {
        if (it + 2 < 8) CP_WAIT1(); else CP_WAIT0();
        __syncthreads();
        if (it + 2 < 8) {
            int s = (it + 2) % NSTG;
            ISSUE_PW(it + 2, s);
        }
        int cs = it % NSTG;
        mma_chunk(smb + cs * STAGE, smb + cs * STAGE + A_BYTES, wm, wn, lane, acc);
    }
#undef ISSUE_PW

    // epilogue: +bias, BN, +identity(fp16), SiLU -> out (fp32)
#pragma unroll
    for (int mf = 0; mf < 4; ++mf) {
        const int oc_a = oc0 + wm * 64 + mf * 16 + (lane >> 2);
        const int oc_b = oc_a + 8;
        const float inva = __ldg(&gamma[oc_a]) * rsqrtf(__ldg(&var[oc_a]) + EPSBN);
        const float bba  = __ldg(&beta[oc_a]) - __ldg(&mean[oc_a]) * inva;
        const float bsa  = __ldg(&b1[oc_a]);
        const float invb = __ldg(&gamma[oc_b]) * rsqrtf(__ldg(&var[oc_b]) + EPSBN);
        const float bbb  = __ldg(&beta[oc_b]) - __ldg(&mean[oc_b]) * invb;
        const float bsb  = __ldg(&b1[oc_b]);
        const size_t ra = ((size_t)b * C2 + oc_a) * HW;
        const size_t rb = ((size_t)b * C2 + oc_b) * HW;
#pragma unroll
        for (int nf = 0; nf < 8; ++nf) {
            const int n = wn * 64 + nf * 8 + (lane & 3) * 2;
            const int off = (h0 + (n >> 7)) * W_ + (n & 127);
            float2 ida = __half22float2(*(const __half2*)(g_yi + ra + off));
            float2 idb = __half22float2(*(const __half2*)(g_yi + rb + off));
            float2 u, v; float z;
            z = (acc[mf][nf][0] + bsa) * inva + bba + ida.x; u.x = silu_f(z);
            z = (acc[mf][nf][1] + bsa) * inva + bba + ida.y; u.y = silu_f(z);
            z = (acc[mf][nf][2] + bsb) * invb + bbb + idb.x; v.x = silu_f(z);
            z = (acc[mf][nf][3] + bsb) * invb + bbb + idb.y; v.y = silu_f(z);
            *(float2*)(out + ra + off) = u;
            *(float2*)(out + rb + off) = v;
        }
    }
}

// ---------------------------------------------------------------------------
extern "C" void kernel_launch(void* const* d_in, const int* in_sizes, int n_in,
                              void* d_out, int out_size)
{
    const float* x     = (const float*)d_in[0];
    const float* wconv = (const float*)d_in[1];
    const float* w1    = (const float*)d_in[2];
    const float* b1    = (const float*)d_in[3];
    const float* gamma = (const float*)d_in[4];
    const float* beta  = (const float*)d_in[5];
    const float* mean  = (const float*)d_in[6];
    const float* var   = (const float*)d_in[7];
    float* out = (float*)d_out;

    static bool attr_done = false;
    if (!attr_done) {
        cudaFuncSetAttribute(k_conv3, cudaFuncAttributeMaxDynamicSharedMemorySize, DSMEM_BYTES);
        cudaFuncSetAttribute(k_pw,    cudaFuncAttributeMaxDynamicSharedMemorySize, DSMEM_BYTES);
        attr_done = true;
    }

    k_repack_conv<<<(C2 * C1 * 9 + 255) / 256, 256>>>(wconv);
    k_repack_pw  <<<(C2 * C2 + 255) / 256, 256>>>(w1);
    k_prep_x     <<<(int)(XVSZ / 8 / 256), 256>>>(x);
    k_zero_sh    <<<(4 * 16 * 64 * 128 + 255) / 256, 256>>>();

    dim3 grid(H_ / 2, 2, B_);
    k_conv3<<<grid, 256, DSMEM_BYTES>>>(gamma, beta, mean, var);
    k_pw   <<<grid, 256, DSMEM_BYTES>>>(b1, gamma, beta, mean, var, out);
}

// round 7
// speedup vs baseline: 13.0489x; 1.0605x over previous
#include <cuda_runtime.h>
#include <cuda_fp16.h>

// SConv R6: R5 pipeline with 512-thread CTAs (16 warps, 4Mx4N, warp 32x64)
// for 2x issue/occupancy. mma.sync m16n8k16 fp16, cp.async 3-stage pipeline,
// all shifts pre-applied in global memory.

#define B_  16
#define C1  128
#define C2  256
#define H_  128
#define W_  128
#define HW  (H_*W_)
#define EPSBN 1e-5f

typedef unsigned int uint;

#define XVSZ ((size_t)B_ * C1 * HW)

__device__ __half g_xv [3 * XVSZ];                // x fp16, col-shift variants -1/0/+1
__device__ __half g_yi [(size_t)B_ * C2 * HW];    // y fp16 plain (identity)
__device__ __half g_ysh[(size_t)B_ * C2 * HW];    // y fp16 pre-shifted per group
__device__ __half g_wA16[36 * 2 * 4096];          // conv w, frag order
__device__ __half g_wB16[ 8 * 2 * 4096];          // 1x1 w, frag order

__device__ __forceinline__ float silu_f(float v) { return v / (1.0f + __expf(-v)); }
__device__ __forceinline__ uint smem_u32(const void* p) {
    uint a;
    asm("{ .reg .u64 t; cvta.to.shared.u64 t, %1; cvt.u32.u64 %0, t; }" : "=r"(a) : "l"(p));
    return a;
}

#define MMA16(d, a, b0v, b1v) \
    asm volatile("mma.sync.aligned.m16n8k16.row.col.f32.f16.f16.f32 " \
        "{%0,%1,%2,%3}, {%4,%5,%6,%7}, {%8,%9}, {%0,%1,%2,%3};" \
        : "+f"((d)[0]), "+f"((d)[1]), "+f"((d)[2]), "+f"((d)[3]) \
        : "r"((a).x), "r"((a).y), "r"((a).z), "r"((a).w), "r"(b0v), "r"(b1v))

#define CP_A16(sm, gp) \
    asm volatile("cp.async.cg.shared.global [%0], [%1], 16;" :: "r"(sm), "l"(gp))
#define CP_A16Z(sm, gp, sz) \
    asm volatile("cp.async.cg.shared.global [%0], [%1], 16, %2;" :: "r"(sm), "l"(gp), "r"(sz))
#define CP_COMMIT() asm volatile("cp.async.commit_group;")
#define CP_WAIT1()  asm volatile("cp.async.wait_group 1;" ::: "memory")
#define CP_WAIT0()  asm volatile("cp.async.wait_group 0;" ::: "memory")

// Stage: A 8192 B (frag order) + B 16384 B (row-major [kk][n], 512B rows,
// 16B-granule XOR swizzle: granule (kk,g) at kk*512 + ((g^(kk&7))<<4)).
#define A_BYTES 8192
#define B_BYTES 16384
#define STAGE   (A_BYTES + B_BYTES)
#define NSTG    3
#define DSMEM_BYTES (NSTG * STAGE)   // 73728

#define NTHR 512

// --------------------------------------------------------- repack kernels --
__device__ __forceinline__ int fragoff(int m, int kk) {
    return (((kk >> 4) * 8 + (m >> 4)) * 32 + (((m & 7) << 2) | ((kk >> 1) & 3))) * 8
         + (((kk >> 3) & 1) * 2 + ((m >> 3) & 1)) * 2 + (kk & 1);
}
__global__ __launch_bounds__(256) void k_repack_conv(const float* __restrict__ wc) {
    int idx = blockIdx.x * 256 + threadIdx.x;
    if (idx >= C2 * C1 * 9) return;
    int tap = idx % 9, rest = idx / 9;
    int ic = rest % C1, oc = rest / C1;
    int it = (ic >> 5) * 9 + tap;
    g_wA16[(size_t)(it * 2 + (oc >> 7)) * 4096 + fragoff(oc & 127, ic & 31)] =
        __float2half_rn(wc[idx]);
}
__global__ __launch_bounds__(256) void k_repack_pw(const float* __restrict__ w1) {
    int idx = blockIdx.x * 256 + threadIdx.x;
    if (idx >= C2 * C2) return;
    int ic = idx % C2, oc = idx / C2;
    g_wB16[(size_t)((ic >> 5) * 2 + (oc >> 7)) * 4096 + fragoff(oc & 127, ic & 31)] =
        __float2half_rn(w1[idx]);
}

__global__ __launch_bounds__(256) void k_prep_x(const float* __restrict__ x) {
    size_t i = (size_t)blockIdx.x * 256 + threadIdx.x;   // over XVSZ/8
    size_t base = i * 8;
    int w0 = (int)(base & 127);
    const float* p = x + base;
    float4 a  = __ldg((const float4*)p);
    float4 b4 = __ldg((const float4*)(p + 4));
    float xm1 = (w0 > 0)   ? __ldg(p - 1) : 0.f;
    float xp8 = (w0 < 120) ? __ldg(p + 8) : 0.f;
    __half2* v0 = (__half2*)g_xv + i * 4;
    __half2* v1 = (__half2*)(g_xv + XVSZ) + i * 4;
    __half2* v2 = (__half2*)(g_xv + 2 * XVSZ) + i * 4;
    v1[0] = __floats2half2_rn(a.x, a.y);  v1[1] = __floats2half2_rn(a.z, a.w);
    v1[2] = __floats2half2_rn(b4.x, b4.y); v1[3] = __floats2half2_rn(b4.z, b4.w);
    v0[0] = __floats2half2_rn(xm1, a.x);  v0[1] = __floats2half2_rn(a.y, a.z);
    v0[2] = __floats2half2_rn(a.w, b4.x); v0[3] = __floats2half2_rn(b4.y, b4.z);
    v2[0] = __floats2half2_rn(a.y, a.z);  v2[1] = __floats2half2_rn(a.w, b4.x);
    v2[2] = __floats2half2_rn(b4.y, b4.z); v2[3] = __floats2half2_rn(b4.w, xp8);
}

__global__ __launch_bounds__(256) void k_zero_sh() {
    int idx = blockIdx.x * 256 + threadIdx.x;   // 524288
    if (idx >= 4 * 16 * 64 * 128) return;
    int grp = idx >> 17, r = idx & 131071;
    int b = r >> 13, r2 = r & 8191;
    int c = r2 >> 7, p = r2 & 127;
    int oc, h, w;
    if      (grp == 0) { oc = c;       h = p;   w = 0;   }
    else if (grp == 1) { oc = 64 + c;  h = 127; w = p;   }
    else if (grp == 2) { oc = 128 + c; h = p;   w = 127; }
    else               { oc = 192 + c; h = 0;   w = p;   }
    g_ysh[(((size_t)b * C2 + oc) << 14) + h * W_ + w] = __float2half_rn(0.f);
}

// --------------------------------------------------------- staging helpers --
__device__ __forceinline__ void cp_issue_A(uint Asm, const __half* src, int tid) {
    CP_A16(Asm + tid * 16, (const char*)src + tid * 16);
}
// B: thread owns granule column g (=tid&31), rows kk0 and kk0+16 (kk0=tid>>5 &15).
__device__ __forceinline__ void cp_issue_B(uint Bsm, const __half* vbase,
                                           int kk0, uint gxor, int hs, int wcol) {
    uint ok = ((uint)hs < 128u) ? 16u : 0u;
    int hsc = (hs < 0) ? 0 : (hs > 127 ? 127 : hs);
    const char* s = (const char*)(vbase + (size_t)kk0 * HW + hsc * W_ + wcol);
    uint d = Bsm + kk0 * 512 + gxor;      // (kk0+16)&7 == kk0&7 -> same gxor
    CP_A16Z(d, s, ok);
    CP_A16Z(d + 16 * 512, s + (size_t)16 * HW * 2, ok);
}

// ----------------------------------------------------------------- MMA -----
// warp tile 32x64: wm=wrp>>2 (0..3), wn=wrp&3. mf in 0..1.
__device__ __forceinline__ void mma_chunk(uint Asm, uint Bsm, int wm, int wn,
                                          int lane, float acc[2][8][4]) {
    const int j = lane >> 3, r = lane & 7;
    const int jk = (j & 1) << 3, jn = j >> 1;
#pragma unroll
    for (int ks = 0; ks < 2; ++ks) {
        uint4 a[2];
#pragma unroll
        for (int mf = 0; mf < 2; ++mf) {
            uint ad = Asm + (((ks * 8 + wm * 2 + mf) * 32 + lane) << 4);
            asm volatile("ld.shared.v4.b32 {%0,%1,%2,%3}, [%4];"
                : "=r"(a[mf].x), "=r"(a[mf].y), "=r"(a[mf].z), "=r"(a[mf].w) : "r"(ad));
        }
        uint bf[8][2];
#pragma unroll
        for (int p = 0; p < 4; ++p) {
            int krow = ks * 16 + jk + r;
            int oct  = wn * 8 + 2 * p + jn;
            uint ad = Bsm + krow * 512 + ((uint)(oct ^ (krow & 7)) << 4);
            uint d0, d1, d2, d3;
            asm volatile("ldmatrix.sync.aligned.m8n8.x4.trans.shared.b16 "
                "{%0,%1,%2,%3}, [%4];"
                : "=r"(d0), "=r"(d1), "=r"(d2), "=r"(d3) : "r"(ad));
            bf[2 * p][0] = d0; bf[2 * p][1] = d1;
            bf[2 * p + 1][0] = d2; bf[2 * p + 1][1] = d3;
        }
#pragma unroll
        for (int mf = 0; mf < 2; ++mf)
#pragma unroll
            for (int nf = 0; nf < 8; ++nf)
                MMA16(acc[mf][nf], a[mf], bf[nf][0], bf[nf][1]);
    }
}

// ------------------------------------------------------ conv3x3 + BN + SiLU
__global__ __launch_bounds__(NTHR, 1) void k_conv3(
    const float* __restrict__ gamma, const float* __restrict__ beta,
    const float* __restrict__ mean,  const float* __restrict__ var)
{
    extern __shared__ __align__(16) char dsm[];
    const uint smb = smem_u32(dsm);

    const int tid = threadIdx.x;
    const int wrp = tid >> 5, lane = tid & 31;
    const int wm = wrp >> 2, wn = wrp & 3;
    const int kk0 = (tid >> 5) & 15, g = tid & 31;
    const int rowsel = g >> 4, wcol = (g & 15) * 8;
    const uint gxor = ((uint)(g ^ (kk0 & 7))) << 4;
    const int h0  = blockIdx.x * 2;
    const int ocg = blockIdx.y, oc0 = ocg * 128;
    const int b   = blockIdx.z;

    float acc[2][8][4];
#pragma unroll
    for (int i = 0; i < 2; ++i)
#pragma unroll
        for (int jj = 0; jj < 8; ++jj)
#pragma unroll
            for (int q = 0; q < 4; ++q) acc[i][jj][q] = 0.0f;

    const size_t bofs = (size_t)b * C1 * HW;
#define ISSUE_CONV(nit, s) do { \
        int kc_ = (nit) / 9, tap_ = (nit) - 9 * kc_; \
        int ky_ = tap_ / 3, kx_ = tap_ - 3 * ky_; \
        cp_issue_A(smb + (s) * STAGE, g_wA16 + (size_t)((nit) * 2 + ocg) * 4096, tid); \
        const __half* vb_ = g_xv + (size_t)kx_ * XVSZ + bofs + (size_t)kc_ * 32 * HW; \
        cp_issue_B(smb + (s) * STAGE + A_BYTES, vb_, kk0, gxor, h0 + rowsel + ky_ - 1, wcol); \
        CP_COMMIT(); \
    } while (0)

    ISSUE_CONV(0, 0);
    ISSUE_CONV(1, 1);

#pragma unroll 1
    for (int it = 0; it < 36; ++it) {
        if (it + 2 < 36) CP_WAIT1(); else CP_WAIT0();
        __syncthreads();
        if (it + 2 < 36) {
            int s = (it + 2) % NSTG;
            ISSUE_CONV(it + 2, s);
        }
        int cs = it % NSTG;
        mma_chunk(smb + cs * STAGE, smb + cs * STAGE + A_BYTES, wm, wn, lane, acc);
    }
#undef ISSUE_CONV

    // epilogue: BN + SiLU -> g_yi (plain) + g_ysh (shifted by group)
    const int grp = ((oc0 + wm * 32) >> 6) & 3;   // warp-uniform
#pragma unroll
    for (int mf = 0; mf < 2; ++mf) {
        const int oc_a = oc0 + wm * 32 + mf * 16 + (lane >> 2);
        const int oc_b = oc_a + 8;
        const float inva = __ldg(&gamma[oc_a]) * rsqrtf(__ldg(&var[oc_a]) + EPSBN);
        const float bba  = __ldg(&beta[oc_a]) - __ldg(&mean[oc_a]) * inva;
        const float invb = __ldg(&gamma[oc_b]) * rsqrtf(__ldg(&var[oc_b]) + EPSBN);
        const float bbb  = __ldg(&beta[oc_b]) - __ldg(&mean[oc_b]) * invb;
        const size_t ra = ((size_t)b * C2 + oc_a) * HW;
        const size_t rb = ((size_t)b * C2 + oc_b) * HW;
#pragma unroll
        for (int nf = 0; nf < 8; ++nf) {
            const int n = wn * 64 + nf * 8 + (lane & 3) * 2;
            const int h = h0 + (n >> 7), w = n & 127;
            const int off = h * W_ + w;
            float2 u, v;
            u.x = silu_f(acc[mf][nf][0] * inva + bba);
            u.y = silu_f(acc[mf][nf][1] * inva + bba);
            v.x = silu_f(acc[mf][nf][2] * invb + bbb);
            v.y = silu_f(acc[mf][nf][3] * invb + bbb);
            __half2 uh = __floats2half2_rn(u.x, u.y);
            __half2 vh = __floats2half2_rn(v.x, v.y);
            *(__half2*)(g_yi + ra + off) = uh;
            *(__half2*)(g_yi + rb + off) = vh;
            if (grp == 0) {            // dest (h, w+1)
                g_ysh[ra + off + 1] = __low2half(uh);
                g_ysh[rb + off + 1] = __low2half(vh);
                if (w < 126) {
                    g_ysh[ra + off + 2] = __high2half(uh);
                    g_ysh[rb + off + 2] = __high2half(vh);
                }
            } else if (grp == 1) {     // dest (h-1, w)
                if (h > 0) {
                    *(__half2*)(g_ysh + ra + off - W_) = uh;
                    *(__half2*)(g_ysh + rb + off - W_) = vh;
                }
            } else if (grp == 2) {     // dest (h, w-1)
                if (w > 0) {
                    g_ysh[ra + off - 1] = __low2half(uh);
                    g_ysh[rb + off - 1] = __low2half(vh);
                }
                g_ysh[ra + off] = __high2half(uh);
                g_ysh[rb + off] = __high2half(vh);
            } else {                   // dest (h+1, w)
                if (h < 127) {
                    *(__half2*)(g_ysh + ra + off + W_) = uh;
                    *(__half2*)(g_ysh + rb + off + W_) = vh;
                }
            }
        }
    }
}

// --------------------------- conv1x1(shifted y) + bias + BN + id + SiLU ----
__global__ __launch_bounds__(NTHR, 1) void k_pw(
    const float* __restrict__ b1,
    const float* __restrict__ gamma, const float* __restrict__ beta,
    const float* __restrict__ mean,  const float* __restrict__ var,
    float* __restrict__ out)
{
    extern __shared__ __align__(16) char dsm[];
    const uint smb = smem_u32(dsm);

    const int tid = threadIdx.x;
    const int wrp = tid >> 5, lane = tid & 31;
    const int wm = wrp >> 2, wn = wrp & 3;
    const int kk0 = (tid >> 5) & 15, g = tid & 31;
    const int rowsel = g >> 4, wcol = (g & 15) * 8;
    const uint gxor = ((uint)(g ^ (kk0 & 7))) << 4;
    const int h0  = blockIdx.x * 2;
    const int ocg = blockIdx.y, oc0 = ocg * 128;
    const int b   = blockIdx.z;

    float acc[2][8][4];
#pragma unroll
    for (int i = 0; i < 2; ++i)
#pragma unroll
        for (int jj = 0; jj < 8; ++jj)
#pragma unroll
            for (int q = 0; q < 4; ++q) acc[i][jj][q] = 0.0f;

    const size_t bofs = (size_t)b * C2 * HW;
#define ISSUE_PW(nit, s) do { \
        cp_issue_A(smb + (s) * STAGE, g_wB16 + (size_t)((nit) * 2 + ocg) * 4096, tid); \
        const __half* vb_ = g_ysh + bofs + (size_t)(nit) * 32 * HW; \
        cp_issue_B(smb + (s) * STAGE + A_BYTES, vb_, kk0, gxor, h0 + rowsel, wcol); \
        CP_COMMIT(); \
    } while (0)

    ISSUE_PW(0, 0);
    ISSUE_PW(1, 1);

#pragma unroll 1
    for (int it = 0; it < 8; ++it) {
        if (it + 2 < 8) CP_WAIT1(); else CP_WAIT0();
        __syncthreads();
        if (it + 2 < 8) {
            int s = (it + 2) % NSTG;
            ISSUE_PW(it + 2, s);
        }
        int cs = it % NSTG;
        mma_chunk(smb + cs * STAGE, smb + cs * STAGE + A_BYTES, wm, wn, lane, acc);
    }
#undef ISSUE_PW

    // epilogue: +bias, BN, +identity(fp16), SiLU -> out (fp32)
#pragma unroll
    for (int mf = 0; mf < 2; ++mf) {
        const int oc_a = oc0 + wm * 32 + mf * 16 + (lane >> 2);
        const int oc_b = oc_a + 8;
        const float inva = __ldg(&gamma[oc_a]) * rsqrtf(__ldg(&var[oc_a]) + EPSBN);
        const float bba  = __ldg(&beta[oc_a]) - __ldg(&mean[oc_a]) * inva;
        const float bsa  = __ldg(&b1[oc_a]);
        const float invb = __ldg(&gamma[oc_b]) * rsqrtf(__ldg(&var[oc_b]) + EPSBN);
        const float bbb  = __ldg(&beta[oc_b]) - __ldg(&mean[oc_b]) * invb;
        const float bsb  = __ldg(&b1[oc_b]);
        const size_t ra = ((size_t)b * C2 + oc_a) * HW;
        const size_t rb = ((size_t)b * C2 + oc_b) * HW;
#pragma unroll
        for (int nf = 0; nf < 8; ++nf) {
            const int n = wn * 64 + nf * 8 + (lane & 3) * 2;
            const int off = (h0 + (n >> 7)) * W_ + (n & 127);
            float2 ida = __half22float2(*(const __half2*)(g_yi + ra + off));
            float2 idb = __half22float2(*(const __half2*)(g_yi + rb + off));
            float2 u, v; float z;
            z = (acc[mf][nf][0] + bsa) * inva + bba + ida.x; u.x = silu_f(z);
            z = (acc[mf][nf][1] + bsa) * inva + bba + ida.y; u.y = silu_f(z);
            z = (acc[mf][nf][2] + bsb) * invb + bbb + idb.x; v.x = silu_f(z);
            z = (acc[mf][nf][3] + bsb) * invb + bbb + idb.y; v.y = silu_f(z);
            *(float2*)(out + ra + off) = u;
            *(float2*)(out + rb + off) = v;
        }
    }
}

// ---------------------------------------------------------------------------
extern "C" void kernel_launch(void* const* d_in, const int* in_sizes, int n_in,
                              void* d_out, int out_size)
{
    const float* x     = (const float*)d_in[0];
    const float* wconv = (const float*)d_in[1];
    const float* w1    = (const float*)d_in[2];
    const float* b1    = (const float*)d_in[3];
    const float* gamma = (const float*)d_in[4];
    const float* beta  = (const float*)d_in[5];
    const float* mean  = (const float*)d_in[6];
    const float* var   = (const float*)d_in[7];
    float* out = (float*)d_out;

    static bool attr_done = false;
    if (!attr_done) {
        cudaFuncSetAttribute(k_conv3, cudaFuncAttributeMaxDynamicSharedMemorySize, DSMEM_BYTES);
        cudaFuncSetAttribute(k_pw,    cudaFuncAttributeMaxDynamicSharedMemorySize, DSMEM_BYTES);
        attr_done = true;
    }

    k_repack_conv<<<(C2 * C1 * 9 + 255) / 256, 256>>>(wconv);
    k_repack_pw  <<<(C2 * C2 + 255) / 256, 256>>>(w1);
    k_prep_x     <<<(int)(XVSZ / 8 / 256), 256>>>(x);
    k_zero_sh    <<<(4 * 16 * 64 * 128 + 255) / 256, 256>>>();

    dim3 grid(H_ / 2, 2, B_);
    k_conv3<<<grid, NTHR, DSMEM_BYTES>>>(gamma, beta, mean, var);
    k_pw   <<<grid, NTHR, DSMEM_BYTES>>>(b1, gamma, beta, mean, var, out);
}